// round 9
// baseline (speedup 1.0000x reference)
#include <cuda_runtime.h>
#include <cuda_bf16.h>
#include <cuda_fp16.h>
#include <stdint.h>
#include <math.h>

#define N_NODES 100000
#define N_EDGES 1600000
#define DIM 128
#define N_LAYERS 3
#define BN_EPS 1e-5f
#define N_TILES 782
#define GRID_P 148

// ---------------- scratch (static device globals; no allocation) ----------------
__device__ float g_bufA[N_NODES * DIM];
__device__ __half2 g_bufH0[N_NODES * DIM / 2];
__device__ __half2 g_bufH1[N_NODES * DIM / 2];
__device__ int g_cnt[N_NODES];
__device__ int g_cur[N_NODES];
__device__ int g_off[N_NODES + 1];
__device__ int g_srcs[N_EDGES];
__device__ int g_is64;
__device__ int g_bsum[128];
__device__ int g_bsumx[128];
#define WIMG_PLANE 34816   // 128*272
#define WIMG_MAT   69632   // 2 planes (hi, lo)
__device__ unsigned char g_Wimg[6 * WIMG_MAT];

__device__ __forceinline__ uint32_t smem_u32(const void* p) {
    uint32_t a;
    asm("{ .reg .u64 t; cvta.to.shared.u64 t, %1; cvt.u32.u64 %0, t; }" : "=r"(a) : "l"(p));
    return a;
}

// ---------------- edge dtype detection ----------------
__global__ void k_detect(const int* __restrict__ e) {
    __shared__ int s;
    if (threadIdx.x == 0) s = 0;
    __syncthreads();
    int v = e[threadIdx.x * 2 + 1];
    if (v != 0) atomicOr(&s, 1);
    __syncthreads();
    if (threadIdx.x == 0) g_is64 = (s == 0) ? 1 : 0;
}
__device__ __forceinline__ int edge_idx(const void* e, int part, int i) {
    if (g_is64) return (int)((const long long*)e)[(size_t)part * N_EDGES + i];
    return ((const int*)e)[(size_t)part * N_EDGES + i];
}

// ---------------- CSR build ----------------
__global__ void k_zero() {
    int i = blockIdx.x * blockDim.x + threadIdx.x;
    if (i < N_NODES) { g_cnt[i] = 0; g_cur[i] = 0; }
}
__global__ void k_hist(const void* __restrict__ e) {
    int i = blockIdx.x * blockDim.x + threadIdx.x;
    if (i < N_EDGES) atomicAdd(&g_cnt[edge_idx(e, 1, i)], 1);
}
__global__ void k_scanA() {
    __shared__ int sh[1024];
    int t = threadIdx.x, i = blockIdx.x * 1024 + t;
    int v = (i < N_NODES) ? g_cnt[i] : 0;
    sh[t] = v; __syncthreads();
    for (int o = 1; o < 1024; o <<= 1) {
        int u = (t >= o) ? sh[t - o] : 0;
        __syncthreads(); sh[t] += u; __syncthreads();
    }
    if (i < N_NODES) g_off[i] = sh[t] - v;
    if (t == 1023) g_bsum[blockIdx.x] = sh[t];
}
__global__ void k_scanB() {
    __shared__ int sh[128];
    int t = threadIdx.x;
    int v = (t < 98) ? g_bsum[t] : 0;
    sh[t] = v; __syncthreads();
    for (int o = 1; o < 128; o <<= 1) {
        int u = (t >= o) ? sh[t - o] : 0;
        __syncthreads(); sh[t] += u; __syncthreads();
    }
    g_bsumx[t] = sh[t] - v;
}
__global__ void k_scanC() {
    int t = threadIdx.x, i = blockIdx.x * 1024 + t;
    if (i < N_NODES) g_off[i] += g_bsumx[blockIdx.x];
    if (i == 0) g_off[N_NODES] = N_EDGES;
}
__global__ void k_scatter(const void* __restrict__ e) {
    int i = blockIdx.x * blockDim.x + threadIdx.x;
    if (i < N_EDGES) {
        int d = edge_idx(e, 1, i);
        int p = g_off[d] + atomicAdd(&g_cur[d], 1);
        g_srcs[p] = edge_idx(e, 0, i);
    }
}

// ---------------- fp16 shadow of x ----------------
__global__ void k_tohalf(const float* __restrict__ X) {
    int i = blockIdx.x * blockDim.x + threadIdx.x;
    if (i >= N_NODES * 32) return;
    float4 v = ((const float4*)X)[i];
    g_bufH0[i * 2]     = __floats2half2_rn(v.x, v.y);
    g_bufH0[i * 2 + 1] = __floats2half2_rn(v.z, v.w);
}

// ---------------- weight image prep ----------------
__global__ void k_wimg(const float* __restrict__ W1, const float* __restrict__ W2) {
    int idx = blockIdx.x * blockDim.x + threadIdx.x;
    if (idx >= 6 * 128 * 64) return;
    int mat = idx >> 13;
    int rem = idx & 8191;
    int n = rem >> 6;
    int kp = rem & 63;
    int k = kp * 2;
    int layer = mat >> 1, which = mat & 1;
    const float* Wsrc = (which ? W2 : W1) + (size_t)layer * DIM * DIM;
    float w0 = Wsrc[k * DIM + n];
    float w1 = Wsrc[(k + 1) * DIM + n];
    __nv_bfloat16 h0 = __float2bfloat16(w0);
    __nv_bfloat16 h1 = __float2bfloat16(w1);
    __nv_bfloat16 l0 = __float2bfloat16(w0 - __bfloat162float(h0));
    __nv_bfloat16 l1 = __float2bfloat16(w1 - __bfloat162float(h1));
    __nv_bfloat162 hp; hp.x = h0; hp.y = h1;
    __nv_bfloat162 lp; lp.x = l0; lp.y = l1;
    int off = mat * WIMG_MAT + n * 272 + kp * 4;
    *(uint32_t*)&g_Wimg[off] = *(uint32_t*)&hp;
    *(uint32_t*)&g_Wimg[off + WIMG_PLANE] = *(uint32_t*)&lp;
}

// ---------------- persistent fused layer: agg + MLP1 + MLP2 (+lsm on last) ----------------
// SMEM: [0..512) scale1, [512..1024) shift1, [1024..1536) shift2,
//       A/Z planes @A_OFF (also fp32 staging, stride 132), W1 @B1_OFF, W2 @B2_OFF.
#define A_OFF 1536
#define B1_OFF (A_OFF + WIMG_MAT)
#define B2_OFF (B1_OFF + WIMG_MAT)
#define TC_SMEM (B2_OFF + WIMG_MAT)

__device__ __forceinline__ void ldsm4(uint32_t addr, uint32_t* r) {
    asm volatile("ldmatrix.sync.aligned.m8n8.x4.shared.b16 {%0,%1,%2,%3}, [%4];"
                 : "=r"(r[0]), "=r"(r[1]), "=r"(r[2]), "=r"(r[3]) : "r"(addr));
}
__device__ __forceinline__ void mma16816(float* c, const uint32_t* a,
                                         uint32_t b0, uint32_t b1) {
    asm volatile("mma.sync.aligned.m16n8k16.row.col.f32.bf16.bf16.f32 "
                 "{%0,%1,%2,%3}, {%4,%5,%6,%7}, {%8,%9}, {%0,%1,%2,%3};"
                 : "+f"(c[0]), "+f"(c[1]), "+f"(c[2]), "+f"(c[3])
                 : "r"(a[0]), "r"(a[1]), "r"(a[2]), "r"(a[3]), "r"(b0), "r"(b1));
}
__device__ __forceinline__ uint32_t bf16pack(float a, float b) {
    __nv_bfloat162 p; p.x = __float2bfloat16(a); p.y = __float2bfloat16(b);
    return *(uint32_t*)&p;
}

__global__ void __launch_bounds__(512, 1)
k_layer(const float* __restrict__ x, float* __restrict__ out, int layer,
        const float* __restrict__ b1, const float* __restrict__ gamma,
        const float* __restrict__ beta, const float* __restrict__ mean,
        const float* __restrict__ var, const float* __restrict__ b2) {
    extern __shared__ char smem[];
    uint32_t sbase = smem_u32(smem);
    int tid = threadIdx.x;
    int wid = tid >> 5, lane = tid & 31;
    int last = (layer == N_LAYERS - 1);

    const float* Xself = layer ? g_bufA : x;
    float* Yout = last ? out : g_bufA;
    const uint2* Hin = (const uint2*)((layer & 1) ? g_bufH1 : g_bufH0);
    __half2* Hout = (layer & 1) ? g_bufH0 : g_bufH1;

    // headers
    if (tid < 128) {
        int c = tid;
        float s = gamma[c] * rsqrtf(var[c] + BN_EPS);
        *(float*)(smem + c * 4) = s;
        *(float*)(smem + 512 + c * 4) = (b1[c] - mean[c]) * s + beta[c];
        *(float*)(smem + 1024 + c * 4) = b2[c];
    }
    // stage weights once
    {
        const float4* s1 = (const float4*)(g_Wimg + (size_t)(layer * 2) * WIMG_MAT);
        const float4* s2 = (const float4*)(g_Wimg + (size_t)(layer * 2 + 1) * WIMG_MAT);
        float4* d1 = (float4*)(smem + B1_OFF);
        float4* d2 = (float4*)(smem + B2_OFF);
        for (int i = tid; i < WIMG_MAT / 16; i += 512) { d1[i] = s1[i]; d2[i] = s2[i]; }
    }

    int wm = wid & 3, wn = wid >> 2;
    float acc[2][4][4];
    uint32_t addrA[2], addrBrel[2];
    #pragma unroll
    for (int mt = 0; mt < 2; mt++)
        addrA[mt] = sbase + A_OFF + (wm * 32 + mt * 16 + (lane & 15)) * 272
                    + (lane >> 4) * 16;
    #pragma unroll
    for (int ntp = 0; ntp < 2; ntp++) {
        int quad = lane >> 3;
        int n = wn * 32 + ntp * 16 + (quad >> 1) * 8 + (lane & 7);
        addrBrel[ntp] = n * 272 + (quad & 1) * 16;
    }

    float* Sf = (float*)(smem + A_OFF);   // fp32 staging view, stride 132

    #define GEMM3(BOFFBASE)                                                        \
    {                                                                              \
        _Pragma("unroll")                                                          \
        for (int mt = 0; mt < 2; mt++)                                             \
            _Pragma("unroll")                                                      \
            for (int nt = 0; nt < 4; nt++)                                         \
                _Pragma("unroll")                                                  \
                for (int j = 0; j < 4; j++) acc[mt][nt][j] = 0.f;                  \
        _Pragma("unroll")                                                          \
        for (int pass = 0; pass < 3; pass++) {                                     \
            uint32_t aOff = (pass == 2) ? WIMG_PLANE : 0;                          \
            uint32_t bOff = (BOFFBASE) + ((pass == 1) ? WIMG_PLANE : 0);           \
            _Pragma("unroll")                                                      \
            for (int ks = 0; ks < 8; ks++) {                                       \
                uint32_t ko = ks * 32;                                             \
                uint32_t afr[2][4], bfr[2][4];                                     \
                _Pragma("unroll")                                                  \
                for (int mt = 0; mt < 2; mt++) ldsm4(addrA[mt] + aOff + ko, afr[mt]); \
                _Pragma("unroll")                                                  \
                for (int ntp = 0; ntp < 2; ntp++)                                  \
                    ldsm4(sbase + addrBrel[ntp] + bOff + ko, bfr[ntp]);            \
                _Pragma("unroll")                                                  \
                for (int mt = 0; mt < 2; mt++)                                     \
                    _Pragma("unroll")                                              \
                    for (int nt = 0; nt < 4; nt++)                                 \
                        mma16816(acc[mt][nt], afr[mt],                             \
                                 bfr[nt >> 1][(nt & 1) * 2],                       \
                                 bfr[nt >> 1][(nt & 1) * 2 + 1]);                  \
            }                                                                      \
        }                                                                          \
    }

    for (int tile = blockIdx.x; tile < N_TILES; tile += GRID_P) {
        int row0 = tile * 128;
        __syncthreads();   // previous tile's GEMM2 / lsm done with A region

        // ---- phase 1: aggregation, warp-per-row, fp32 into Sf ----
        #pragma unroll
        for (int j = 0; j < 8; j++) {
            int r = wid * 8 + j;
            int grow = row0 + r;
            float4 a = make_float4(0.f, 0.f, 0.f, 0.f);
            if (grow < N_NODES) {
                a = ((const float4*)Xself)[(size_t)grow * 32 + lane];
                int e0 = g_off[grow], e1 = g_off[grow + 1];
                for (int e = e0; e < e1; e++) {
                    int s = g_srcs[e];
                    uint2 u = __ldg(&Hin[(size_t)s * 32 + lane]);
                    float2 f0 = __half22float2(*(__half2*)&u.x);
                    float2 f1 = __half22float2(*(__half2*)&u.y);
                    a.x += f0.x; a.y += f0.y; a.z += f1.x; a.w += f1.y;
                }
            }
            *(float4*)&Sf[r * 132 + lane * 4] = a;
        }
        __syncthreads();

        // ---- phase 2: fp32 Sf -> bf16 hi/lo A planes (in place over region) ----
        {
            int r = tid >> 2, q = tid & 3;
            float4 v[8];
            #pragma unroll
            for (int p = 0; p < 8; p++) v[p] = *(float4*)&Sf[r * 132 + q * 32 + p * 4];
            __syncthreads();
            char* arow = smem + A_OFF + r * 272;
            #pragma unroll
            for (int p = 0; p < 8; p++) {
                int kb = (q * 32 + p * 4) * 2;
                __nv_bfloat16 hx = __float2bfloat16(v[p].x), hy = __float2bfloat16(v[p].y);
                __nv_bfloat16 hz = __float2bfloat16(v[p].z), hw = __float2bfloat16(v[p].w);
                __nv_bfloat162 h01; h01.x = hx; h01.y = hy;
                __nv_bfloat162 h23; h23.x = hz; h23.y = hw;
                __nv_bfloat162 l01, l23;
                l01.x = __float2bfloat16(v[p].x - __bfloat162float(hx));
                l01.y = __float2bfloat16(v[p].y - __bfloat162float(hy));
                l23.x = __float2bfloat16(v[p].z - __bfloat162float(hz));
                l23.y = __float2bfloat16(v[p].w - __bfloat162float(hw));
                *(uint32_t*)(arow + kb)     = *(uint32_t*)&h01;
                *(uint32_t*)(arow + kb + 4) = *(uint32_t*)&h23;
                *(uint32_t*)(arow + WIMG_PLANE + kb)     = *(uint32_t*)&l01;
                *(uint32_t*)(arow + WIMG_PLANE + kb + 4) = *(uint32_t*)&l23;
            }
        }
        __syncthreads();

        // ---- GEMM1 ----
        GEMM3(B1_OFF);
        __syncthreads();

        // ---- epilogue1: BN+ReLU -> Z planes (overwrite A region) ----
        {
            char* base = smem + A_OFF;
            #pragma unroll
            for (int mt = 0; mt < 2; mt++) {
                #pragma unroll
                for (int nt = 0; nt < 4; nt++) {
                    int n = wn * 32 + nt * 8 + (lane & 3) * 2;
                    float2 sc = *(float2*)(smem + n * 4);
                    float2 sh = *(float2*)(smem + 512 + n * 4);
                    int lr1 = wm * 32 + mt * 16 + (lane >> 2);
                    int lr2 = lr1 + 8;
                    float* c = acc[mt][nt];
                    float z0 = fmaxf(fmaf(c[0], sc.x, sh.x), 0.f);
                    float z1 = fmaxf(fmaf(c[1], sc.y, sh.y), 0.f);
                    float z2 = fmaxf(fmaf(c[2], sc.x, sh.x), 0.f);
                    float z3 = fmaxf(fmaf(c[3], sc.y, sh.y), 0.f);
                    __nv_bfloat16 h0 = __float2bfloat16(z0), h1 = __float2bfloat16(z1);
                    __nv_bfloat16 h2 = __float2bfloat16(z2), h3 = __float2bfloat16(z3);
                    *(uint32_t*)(base + lr1 * 272 + n * 2) = bf16pack(z0, z1);
                    *(uint32_t*)(base + WIMG_PLANE + lr1 * 272 + n * 2) =
                        bf16pack(z0 - __bfloat162float(h0), z1 - __bfloat162float(h1));
                    *(uint32_t*)(base + lr2 * 272 + n * 2) = bf16pack(z2, z3);
                    *(uint32_t*)(base + WIMG_PLANE + lr2 * 272 + n * 2) =
                        bf16pack(z2 - __bfloat162float(h2), z3 - __bfloat162float(h3));
                }
            }
        }
        __syncthreads();

        // ---- GEMM2 ----
        GEMM3(B2_OFF);

        if (!last) {
            // epilogue2: bias+ReLU -> gmem fp32 + fp16 shadow
            #pragma unroll
            for (int mt = 0; mt < 2; mt++) {
                #pragma unroll
                for (int nt = 0; nt < 4; nt++) {
                    int n = wn * 32 + nt * 8 + (lane & 3) * 2;
                    float2 sh = *(float2*)(smem + 1024 + n * 4);
                    int r1 = row0 + wm * 32 + mt * 16 + (lane >> 2);
                    int r2 = r1 + 8;
                    float* c = acc[mt][nt];
                    if (r1 < N_NODES) {
                        float2 o;
                        o.x = fmaxf(c[0] + sh.x, 0.f);
                        o.y = fmaxf(c[1] + sh.y, 0.f);
                        *(float2*)(Yout + (size_t)r1 * DIM + n) = o;
                        Hout[(size_t)r1 * 64 + (n >> 1)] = __floats2half2_rn(o.x, o.y);
                    }
                    if (r2 < N_NODES) {
                        float2 o;
                        o.x = fmaxf(c[2] + sh.x, 0.f);
                        o.y = fmaxf(c[3] + sh.y, 0.f);
                        *(float2*)(Yout + (size_t)r2 * DIM + n) = o;
                        Hout[(size_t)r2 * 64 + (n >> 1)] = __floats2half2_rn(o.x, o.y);
                    }
                }
            }
        } else {
            // epilogue2 + fused log-softmax
            __syncthreads();   // GEMM2 ldsm reads of A region done; reuse as fp32 buf
            #pragma unroll
            for (int mt = 0; mt < 2; mt++) {
                #pragma unroll
                for (int nt = 0; nt < 4; nt++) {
                    int n = wn * 32 + nt * 8 + (lane & 3) * 2;
                    float2 sh = *(float2*)(smem + 1024 + n * 4);
                    int lr1 = wm * 32 + mt * 16 + (lane >> 2);
                    int lr2 = lr1 + 8;
                    float* c = acc[mt][nt];
                    float2 o1, o2;
                    o1.x = fmaxf(c[0] + sh.x, 0.f);
                    o1.y = fmaxf(c[1] + sh.y, 0.f);
                    o2.x = fmaxf(c[2] + sh.x, 0.f);
                    o2.y = fmaxf(c[3] + sh.y, 0.f);
                    *(float2*)&Sf[lr1 * 132 + n] = o1;
                    *(float2*)&Sf[lr2 * 132 + n] = o2;
                }
            }
            __syncthreads();
            #pragma unroll
            for (int j = 0; j < 8; j++) {
                int r = wid * 8 + j;
                int grow = row0 + r;
                float4 v = *(float4*)&Sf[r * 132 + lane * 4];
                float m = fmaxf(fmaxf(v.x, v.y), fmaxf(v.z, v.w));
                #pragma unroll
                for (int o = 16; o; o >>= 1) m = fmaxf(m, __shfl_xor_sync(0xffffffffu, m, o));
                float s = expf(v.x - m) + expf(v.y - m) + expf(v.z - m) + expf(v.w - m);
                #pragma unroll
                for (int o = 16; o; o >>= 1) s += __shfl_xor_sync(0xffffffffu, s, o);
                float ls = m + logf(s);
                if (grow < N_NODES)
                    ((float4*)Yout)[(size_t)grow * 32 + lane] =
                        make_float4(v.x - ls, v.y - ls, v.z - ls, v.w - ls);
            }
        }
    }
    #undef GEMM3
}

// ---------------- launch ----------------
extern "C" void kernel_launch(void* const* d_in, const int* in_sizes, int n_in,
                              void* d_out, int out_size) {
    const float* x     = (const float*)d_in[0];
    const void* ei     = d_in[1];
    const float* W1    = (const float*)d_in[2];
    const float* b1    = (const float*)d_in[3];
    const float* gamma = (const float*)d_in[4];
    const float* beta  = (const float*)d_in[5];
    const float* rmean = (const float*)d_in[6];
    const float* rvar  = (const float*)d_in[7];
    const float* W2    = (const float*)d_in[8];
    const float* b2    = (const float*)d_in[9];
    float* out = (float*)d_out;

    cudaFuncSetAttribute(k_layer, cudaFuncAttributeMaxDynamicSharedMemorySize, TC_SMEM);

    k_detect<<<1, 1024>>>((const int*)ei);
    k_zero<<<(N_NODES + 255) / 256, 256>>>();
    k_wimg<<<(6 * 128 * 64 + 255) / 256, 256>>>(W1, W2);
    k_tohalf<<<(N_NODES * 32 + 255) / 256, 256>>>(x);
    k_hist<<<(N_EDGES + 255) / 256, 256>>>(ei);
    k_scanA<<<98, 1024>>>();
    k_scanB<<<1, 128>>>();
    k_scanC<<<98, 1024>>>();
    k_scatter<<<(N_EDGES + 255) / 256, 256>>>(ei);

    for (int l = 0; l < N_LAYERS; l++) {
        k_layer<<<GRID_P, 512, TC_SMEM>>>(x, out, l,
                                          b1 + l * DIM, gamma + l * DIM,
                                          beta + l * DIM, rmean + l * DIM,
                                          rvar + l * DIM, b2 + l * DIM);
    }
}

// round 10
// speedup vs baseline: 1.3898x; 1.3898x over previous
#include <cuda_runtime.h>
#include <cuda_fp16.h>
#include <stdint.h>
#include <math.h>

#define N_NODES 100000
#define N_EDGES 1600000
#define DIM 128
#define N_LAYERS 3
#define BN_EPS 1e-5f

// ---------------- scratch (static device globals; no allocation) ----------------
__device__ float g_bufA[N_NODES * DIM];
__device__ float g_bufB[N_NODES * DIM];
__device__ __half2 g_bufH[N_NODES * DIM / 2];   // fp16 shadow for gathers
__device__ int g_cnt[N_NODES];
__device__ int g_cur[N_NODES];
__device__ int g_off[N_NODES + 1];
__device__ int g_srcs[N_EDGES];
__device__ int g_is64;
__device__ int g_bsum[128];
__device__ int g_bsumx[128];
// Pre-built padded SMEM image of B = W^T, single fp16 plane:
// per matrix: 128 n-rows x 136 fp16 (272B, k-major).
#define WIMG_MAT 34816   // 128*272
__device__ unsigned char g_Wimg[6 * WIMG_MAT];

__device__ __forceinline__ float* bufptr(int s) { return s ? g_bufB : g_bufA; }

__device__ __forceinline__ uint32_t smem_u32(const void* p) {
    uint32_t a;
    asm("{ .reg .u64 t; cvta.to.shared.u64 t, %1; cvt.u32.u64 %0, t; }" : "=r"(a) : "l"(p));
    return a;
}

// ---------------- edge dtype detection ----------------
__global__ void k_detect(const int* __restrict__ e) {
    __shared__ int s;
    if (threadIdx.x == 0) s = 0;
    __syncthreads();
    int v = e[threadIdx.x * 2 + 1];
    if (v != 0) atomicOr(&s, 1);
    __syncthreads();
    if (threadIdx.x == 0) g_is64 = (s == 0) ? 1 : 0;
}
__device__ __forceinline__ int edge_idx(const void* e, int part, int i) {
    if (g_is64) return (int)((const long long*)e)[(size_t)part * N_EDGES + i];
    return ((const int*)e)[(size_t)part * N_EDGES + i];
}

// ---------------- CSR build ----------------
__global__ void k_zero() {
    int i = blockIdx.x * blockDim.x + threadIdx.x;
    if (i < N_NODES) { g_cnt[i] = 0; g_cur[i] = 0; }
}
__global__ void k_hist(const void* __restrict__ e) {
    int i = blockIdx.x * blockDim.x + threadIdx.x;
    if (i < N_EDGES) atomicAdd(&g_cnt[edge_idx(e, 1, i)], 1);
}
__global__ void k_scanA() {
    __shared__ int sh[1024];
    int t = threadIdx.x, i = blockIdx.x * 1024 + t;
    int v = (i < N_NODES) ? g_cnt[i] : 0;
    sh[t] = v; __syncthreads();
    for (int o = 1; o < 1024; o <<= 1) {
        int u = (t >= o) ? sh[t - o] : 0;
        __syncthreads(); sh[t] += u; __syncthreads();
    }
    if (i < N_NODES) g_off[i] = sh[t] - v;
    if (t == 1023) g_bsum[blockIdx.x] = sh[t];
}
__global__ void k_scanB() {
    __shared__ int sh[128];
    int t = threadIdx.x;
    int v = (t < 98) ? g_bsum[t] : 0;
    sh[t] = v; __syncthreads();
    for (int o = 1; o < 128; o <<= 1) {
        int u = (t >= o) ? sh[t - o] : 0;
        __syncthreads(); sh[t] += u; __syncthreads();
    }
    g_bsumx[t] = sh[t] - v;
}
__global__ void k_scanC() {
    int t = threadIdx.x, i = blockIdx.x * 1024 + t;
    if (i < N_NODES) g_off[i] += g_bsumx[blockIdx.x];
    if (i == 0) g_off[N_NODES] = N_EDGES;
}
__global__ void k_scatter(const void* __restrict__ e) {
    int i = blockIdx.x * blockDim.x + threadIdx.x;
    if (i < N_EDGES) {
        int d = edge_idx(e, 1, i);
        int p = g_off[d] + atomicAdd(&g_cur[d], 1);
        g_srcs[p] = edge_idx(e, 0, i);
    }
}

// ---------------- fp16 shadow of x ----------------
__global__ void k_tohalf(const float* __restrict__ X) {
    int i = blockIdx.x * blockDim.x + threadIdx.x;
    if (i >= N_NODES * 32) return;
    float4 v = ((const float4*)X)[i];
    g_bufH[i * 2]     = __floats2half2_rn(v.x, v.y);
    g_bufH[i * 2 + 1] = __floats2half2_rn(v.z, v.w);
}

// ---------------- aggregation: self fp32 + fp16 neighbor gather, 4x unroll ----------------
__global__ void k_agg(const float* __restrict__ X0, int in_sel, int out_sel) {
    int warp = (blockIdx.x * blockDim.x + threadIdx.x) >> 5;
    if (warp >= N_NODES) return;
    int lane = threadIdx.x & 31;
    const float* H = (in_sel < 0) ? X0 : bufptr(in_sel);
    float* O = bufptr(out_sel);
    float4 a = ((const float4*)H)[(size_t)warp * 32 + lane];
    const uint2* H2 = (const uint2*)g_bufH;
    int e = g_off[warp], e1 = g_off[warp + 1];
    for (; e + 4 <= e1; e += 4) {
        int s0 = g_srcs[e], s1 = g_srcs[e + 1], s2 = g_srcs[e + 2], s3 = g_srcs[e + 3];
        uint2 u0 = __ldg(&H2[(size_t)s0 * 32 + lane]);
        uint2 u1 = __ldg(&H2[(size_t)s1 * 32 + lane]);
        uint2 u2 = __ldg(&H2[(size_t)s2 * 32 + lane]);
        uint2 u3 = __ldg(&H2[(size_t)s3 * 32 + lane]);
        float2 f;
        f = __half22float2(*(__half2*)&u0.x); a.x += f.x; a.y += f.y;
        f = __half22float2(*(__half2*)&u0.y); a.z += f.x; a.w += f.y;
        f = __half22float2(*(__half2*)&u1.x); a.x += f.x; a.y += f.y;
        f = __half22float2(*(__half2*)&u1.y); a.z += f.x; a.w += f.y;
        f = __half22float2(*(__half2*)&u2.x); a.x += f.x; a.y += f.y;
        f = __half22float2(*(__half2*)&u2.y); a.z += f.x; a.w += f.y;
        f = __half22float2(*(__half2*)&u3.x); a.x += f.x; a.y += f.y;
        f = __half22float2(*(__half2*)&u3.y); a.z += f.x; a.w += f.y;
    }
    for (; e < e1; e++) {
        int s = g_srcs[e];
        uint2 u = __ldg(&H2[(size_t)s * 32 + lane]);
        float2 f0 = __half22float2(*(__half2*)&u.x);
        float2 f1 = __half22float2(*(__half2*)&u.y);
        a.x += f0.x; a.y += f0.y; a.z += f1.x; a.w += f1.y;
    }
    ((float4*)O)[(size_t)warp * 32 + lane] = a;
}

// ---------------- weight image prep (padded fp16 B image, single plane) ----------------
__global__ void k_wimg(const float* __restrict__ W1, const float* __restrict__ W2) {
    int idx = blockIdx.x * blockDim.x + threadIdx.x;  // 6 * 128 * 64
    if (idx >= 6 * 128 * 64) return;
    int mat = idx >> 13;
    int rem = idx & 8191;
    int n = rem >> 6;              // output column = B row
    int kp = rem & 63;             // k pair
    int k = kp * 2;
    int layer = mat >> 1, which = mat & 1;
    const float* Wsrc = (which ? W2 : W1) + (size_t)layer * DIM * DIM;
    __half2 p = __floats2half2_rn(Wsrc[k * DIM + n], Wsrc[(k + 1) * DIM + n]);
    *(uint32_t*)&g_Wimg[mat * WIMG_MAT + n * 272 + kp * 4] = *(uint32_t*)&p;
}

// ---------------- fused 2-GEMM MLP (HMMA fp16, single pass) ----------------
// Z = relu(BN(X@W1+b1)); Y = relu(Z@W2+b2). Z lives only in SMEM.
// SMEM: [0..512) scale1, [512..1024) shift1, [1024..1536) shift2,
//       A/Z plane @A_OFF, W1 @B1_OFF, W2 @B2_OFF.   Total ~104 KB -> 2 CTAs/SM.
#define A_OFF 1536
#define B1_OFF (A_OFF + WIMG_MAT)
#define B2_OFF (B1_OFF + WIMG_MAT)
#define TC_SMEM (B2_OFF + WIMG_MAT)

__device__ __forceinline__ void ldsm4(uint32_t addr, uint32_t* r) {
    asm volatile("ldmatrix.sync.aligned.m8n8.x4.shared.b16 {%0,%1,%2,%3}, [%4];"
                 : "=r"(r[0]), "=r"(r[1]), "=r"(r[2]), "=r"(r[3]) : "r"(addr));
}
__device__ __forceinline__ void mma16816(float* c, const uint32_t* a,
                                         uint32_t b0, uint32_t b1) {
    asm volatile("mma.sync.aligned.m16n8k16.row.col.f32.f16.f16.f32 "
                 "{%0,%1,%2,%3}, {%4,%5,%6,%7}, {%8,%9}, {%0,%1,%2,%3};"
                 : "+f"(c[0]), "+f"(c[1]), "+f"(c[2]), "+f"(c[3])
                 : "r"(a[0]), "r"(a[1]), "r"(a[2]), "r"(a[3]), "r"(b0), "r"(b1));
}

__global__ void __launch_bounds__(512, 2)
k_mlp_fused(int in_sel, int out_sel, int mat1, int mat2, int write_half,
            const float* __restrict__ b1, const float* __restrict__ gamma,
            const float* __restrict__ beta, const float* __restrict__ mean,
            const float* __restrict__ var, const float* __restrict__ b2) {
    extern __shared__ char smem[];
    uint32_t sbase = smem_u32(smem);
    int tid = threadIdx.x;
    int wid = tid >> 5, lane = tid & 31;
    int row0 = blockIdx.x * 128;
    const float* X = bufptr(in_sel);
    float* Y = bufptr(out_sel);

    // headers
    if (tid < 128) {
        int c = tid;
        float s = gamma[c] * rsqrtf(var[c] + BN_EPS);
        *(float*)(smem + c * 4) = s;
        *(float*)(smem + 512 + c * 4) = (b1[c] - mean[c]) * s + beta[c];
        *(float*)(smem + 1024 + c * 4) = b2[c];
    }
    // stage W1 + W2 images (flat copies)
    {
        const float4* s1 = (const float4*)(g_Wimg + (size_t)mat1 * WIMG_MAT);
        const float4* s2 = (const float4*)(g_Wimg + (size_t)mat2 * WIMG_MAT);
        float4* d1 = (float4*)(smem + B1_OFF);
        float4* d2 = (float4*)(smem + B2_OFF);
        for (int i = tid; i < WIMG_MAT / 16; i += 512) { d1[i] = s1[i]; d2[i] = s2[i]; }
    }
    // stage A: fp32 -> fp16 plane (4 threads per row)
    {
        int r = tid >> 2, q = tid & 3;
        bool valid = (row0 + r) < N_NODES;
        const float4* xr = (const float4*)X + (size_t)(row0 + r) * 32 + q * 8;
        char* arow = smem + A_OFF + r * 272;
        #pragma unroll
        for (int p = 0; p < 8; p++) {
            float4 v = valid ? __ldg(&xr[p]) : make_float4(0.f, 0.f, 0.f, 0.f);
            int kb = (q * 32 + p * 4) * 2;
            __half2 h01 = __floats2half2_rn(v.x, v.y);
            __half2 h23 = __floats2half2_rn(v.z, v.w);
            *(uint32_t*)(arow + kb)     = *(uint32_t*)&h01;
            *(uint32_t*)(arow + kb + 4) = *(uint32_t*)&h23;
        }
    }
    __syncthreads();

    int wm = wid & 3, wn = wid >> 2;
    float acc[2][4][4];
    uint32_t addrA[2], addrBrel[2];
    #pragma unroll
    for (int mt = 0; mt < 2; mt++)
        addrA[mt] = sbase + A_OFF + (wm * 32 + mt * 16 + (lane & 15)) * 272
                    + (lane >> 4) * 16;
    #pragma unroll
    for (int ntp = 0; ntp < 2; ntp++) {
        int quad = lane >> 3;
        int n = wn * 32 + ntp * 16 + (quad >> 1) * 8 + (lane & 7);
        addrBrel[ntp] = n * 272 + (quad & 1) * 16;
    }

    #define GEMM1P(BOFFBASE)                                                       \
    {                                                                              \
        _Pragma("unroll")                                                          \
        for (int mt = 0; mt < 2; mt++)                                             \
            _Pragma("unroll")                                                      \
            for (int nt = 0; nt < 4; nt++)                                         \
                _Pragma("unroll")                                                  \
                for (int j = 0; j < 4; j++) acc[mt][nt][j] = 0.f;                  \
        _Pragma("unroll")                                                          \
        for (int ks = 0; ks < 8; ks++) {                                           \
            uint32_t ko = ks * 32;                                                 \
            uint32_t afr[2][4], bfr[2][4];                                         \
            _Pragma("unroll")                                                      \
            for (int mt = 0; mt < 2; mt++) ldsm4(addrA[mt] + ko, afr[mt]);         \
            _Pragma("unroll")                                                      \
            for (int ntp = 0; ntp < 2; ntp++)                                      \
                ldsm4(sbase + addrBrel[ntp] + (BOFFBASE) + ko, bfr[ntp]);          \
            _Pragma("unroll")                                                      \
            for (int mt = 0; mt < 2; mt++)                                         \
                _Pragma("unroll")                                                  \
                for (int nt = 0; nt < 4; nt++)                                     \
                    mma16816(acc[mt][nt], afr[mt],                                 \
                             bfr[nt >> 1][(nt & 1) * 2],                           \
                             bfr[nt >> 1][(nt & 1) * 2 + 1]);                      \
        }                                                                          \
    }

    // GEMM1
    GEMM1P(B1_OFF);
    __syncthreads();   // all ldsm reads of A done before Z overwrites

    // epilogue1: BN+ReLU -> fp16 Z plane (overwrite A region)
    {
        char* base = smem + A_OFF;
        #pragma unroll
        for (int mt = 0; mt < 2; mt++) {
            #pragma unroll
            for (int nt = 0; nt < 4; nt++) {
                int n = wn * 32 + nt * 8 + (lane & 3) * 2;
                float2 sc = *(float2*)(smem + n * 4);
                float2 sh = *(float2*)(smem + 512 + n * 4);
                int lr1 = wm * 32 + mt * 16 + (lane >> 2);
                int lr2 = lr1 + 8;
                float* c = acc[mt][nt];
                __half2 z1 = __floats2half2_rn(fmaxf(fmaf(c[0], sc.x, sh.x), 0.f),
                                               fmaxf(fmaf(c[1], sc.y, sh.y), 0.f));
                __half2 z2 = __floats2half2_rn(fmaxf(fmaf(c[2], sc.x, sh.x), 0.f),
                                               fmaxf(fmaf(c[3], sc.y, sh.y), 0.f));
                *(uint32_t*)(base + lr1 * 272 + n * 2) = *(uint32_t*)&z1;
                *(uint32_t*)(base + lr2 * 272 + n * 2) = *(uint32_t*)&z2;
            }
        }
    }
    __syncthreads();

    // GEMM2
    GEMM1P(B2_OFF);

    // epilogue2: bias+ReLU -> Y fp32 (+ fp16 shadow)
    #pragma unroll
    for (int mt = 0; mt < 2; mt++) {
        #pragma unroll
        for (int nt = 0; nt < 4; nt++) {
            int n = wn * 32 + nt * 8 + (lane & 3) * 2;
            float2 sh = *(float2*)(smem + 1024 + n * 4);
            int r1 = row0 + wm * 32 + mt * 16 + (lane >> 2);
            int r2 = r1 + 8;
            float* c = acc[mt][nt];
            if (r1 < N_NODES) {
                float2 o;
                o.x = fmaxf(c[0] + sh.x, 0.f);
                o.y = fmaxf(c[1] + sh.y, 0.f);
                *(float2*)(Y + (size_t)r1 * DIM + n) = o;
                if (write_half) g_bufH[(size_t)r1 * 64 + (n >> 1)] = __floats2half2_rn(o.x, o.y);
            }
            if (r2 < N_NODES) {
                float2 o;
                o.x = fmaxf(c[2] + sh.x, 0.f);
                o.y = fmaxf(c[3] + sh.y, 0.f);
                *(float2*)(Y + (size_t)r2 * DIM + n) = o;
                if (write_half) g_bufH[(size_t)r2 * 64 + (n >> 1)] = __floats2half2_rn(o.x, o.y);
            }
        }
    }
    #undef GEMM1P
}

// ---------------- log-softmax (warp per row) ----------------
__global__ void k_lsm(int in_sel, float* __restrict__ Y) {
    int warp = (blockIdx.x * blockDim.x + threadIdx.x) >> 5;
    if (warp >= N_NODES) return;
    int lane = threadIdx.x & 31;
    const float* X = bufptr(in_sel);
    float4 v = ((const float4*)X)[(size_t)warp * 32 + lane];
    float m = fmaxf(fmaxf(v.x, v.y), fmaxf(v.z, v.w));
    #pragma unroll
    for (int o = 16; o; o >>= 1) m = fmaxf(m, __shfl_xor_sync(0xffffffffu, m, o));
    float s = expf(v.x - m) + expf(v.y - m) + expf(v.z - m) + expf(v.w - m);
    #pragma unroll
    for (int o = 16; o; o >>= 1) s += __shfl_xor_sync(0xffffffffu, s, o);
    float ls = m + logf(s);
    ((float4*)Y)[(size_t)warp * 32 + lane] =
        make_float4(v.x - ls, v.y - ls, v.z - ls, v.w - ls);
}

// ---------------- launch ----------------
extern "C" void kernel_launch(void* const* d_in, const int* in_sizes, int n_in,
                              void* d_out, int out_size) {
    const float* x     = (const float*)d_in[0];
    const void* ei     = d_in[1];
    const float* W1    = (const float*)d_in[2];
    const float* b1    = (const float*)d_in[3];
    const float* gamma = (const float*)d_in[4];
    const float* beta  = (const float*)d_in[5];
    const float* rmean = (const float*)d_in[6];
    const float* rvar  = (const float*)d_in[7];
    const float* W2    = (const float*)d_in[8];
    const float* b2    = (const float*)d_in[9];
    float* out = (float*)d_out;

    cudaFuncSetAttribute(k_mlp_fused, cudaFuncAttributeMaxDynamicSharedMemorySize, TC_SMEM);

    k_detect<<<1, 1024>>>((const int*)ei);
    k_zero<<<(N_NODES + 255) / 256, 256>>>();
    k_wimg<<<(6 * 128 * 64 + 255) / 256, 256>>>(W1, W2);
    k_tohalf<<<(N_NODES * 32 + 255) / 256, 256>>>(x);
    k_hist<<<(N_EDGES + 255) / 256, 256>>>(ei);
    k_scanA<<<98, 1024>>>();
    k_scanB<<<1, 128>>>();
    k_scanC<<<98, 1024>>>();
    k_scatter<<<(N_EDGES + 255) / 256, 256>>>(ei);

    const int AGG_BLOCKS = (N_NODES * 32 + 255) / 256;
    const int MLP_BLOCKS = (N_NODES + 127) / 128;

    int cur = -1;  // self-term source: x
    for (int l = 0; l < N_LAYERS; l++) {
        k_agg<<<AGG_BLOCKS, 256>>>(x, cur, 0);
        k_mlp_fused<<<MLP_BLOCKS, 512, TC_SMEM>>>(0, 1, l * 2, l * 2 + 1,
                                                  (l < N_LAYERS - 1) ? 1 : 0,
                                                  b1 + l * DIM, gamma + l * DIM,
                                                  beta + l * DIM, rmean + l * DIM,
                                                  rvar + l * DIM, b2 + l * DIM);
        cur = 1;
    }
    k_lsm<<<AGG_BLOCKS, 256>>>(1, out);
}

// round 11
// speedup vs baseline: 2.2066x; 1.5878x over previous
#include <cuda_runtime.h>
#include <cuda_fp16.h>
#include <stdint.h>
#include <math.h>

#define N_NODES 100000
#define N_EDGES 1600000
#define DIM 128
#define N_LAYERS 3
#define BN_EPS 1e-5f

// ---------------- scratch (static device globals; no allocation) ----------------
__device__ float g_bufF[N_NODES * DIM];          // fp32 buffer (last-layer output for lsm)
__device__ __half2 g_H0[N_NODES * DIM / 2];      // fp16 node features (ping)
__device__ __half2 g_H1[N_NODES * DIM / 2];      // fp16 node features (pong)
__device__ __half2 g_T[N_NODES * DIM / 2];       // fp16 agg output
__device__ int g_cnt[N_NODES];
__device__ int g_cur[N_NODES];
__device__ int g_off[N_NODES + 1];
__device__ int g_srcs[N_EDGES];
__device__ int g_is64;
__device__ int g_bsum[128];
__device__ int g_bsumx[128];
// Pre-built padded SMEM image of B = W^T, single fp16 plane:
// per matrix: 128 n-rows x 136 fp16 (272B, k-major).
#define WIMG_MAT 34816   // 128*272
__device__ unsigned char g_Wimg[6 * WIMG_MAT];

__device__ __forceinline__ uint32_t smem_u32(const void* p) {
    uint32_t a;
    asm("{ .reg .u64 t; cvta.to.shared.u64 t, %1; cvt.u32.u64 %0, t; }" : "=r"(a) : "l"(p));
    return a;
}

// ---------------- edge dtype detection ----------------
__global__ void k_detect(const int* __restrict__ e) {
    __shared__ int s;
    if (threadIdx.x == 0) s = 0;
    __syncthreads();
    int v = e[threadIdx.x * 2 + 1];
    if (v != 0) atomicOr(&s, 1);
    __syncthreads();
    if (threadIdx.x == 0) g_is64 = (s == 0) ? 1 : 0;
}
__device__ __forceinline__ int edge_idx(const void* e, int part, int i) {
    if (g_is64) return (int)((const long long*)e)[(size_t)part * N_EDGES + i];
    return ((const int*)e)[(size_t)part * N_EDGES + i];
}

// ---------------- CSR build ----------------
__global__ void k_zero() {
    int i = blockIdx.x * blockDim.x + threadIdx.x;
    if (i < N_NODES) { g_cnt[i] = 0; g_cur[i] = 0; }
}
__global__ void k_hist(const void* __restrict__ e) {
    int i = blockIdx.x * blockDim.x + threadIdx.x;
    if (i < N_EDGES) atomicAdd(&g_cnt[edge_idx(e, 1, i)], 1);
}
__global__ void k_scanA() {
    __shared__ int sh[1024];
    int t = threadIdx.x, i = blockIdx.x * 1024 + t;
    int v = (i < N_NODES) ? g_cnt[i] : 0;
    sh[t] = v; __syncthreads();
    for (int o = 1; o < 1024; o <<= 1) {
        int u = (t >= o) ? sh[t - o] : 0;
        __syncthreads(); sh[t] += u; __syncthreads();
    }
    if (i < N_NODES) g_off[i] = sh[t] - v;
    if (t == 1023) g_bsum[blockIdx.x] = sh[t];
}
__global__ void k_scanB() {
    __shared__ int sh[128];
    int t = threadIdx.x;
    int v = (t < 98) ? g_bsum[t] : 0;
    sh[t] = v; __syncthreads();
    for (int o = 1; o < 128; o <<= 1) {
        int u = (t >= o) ? sh[t - o] : 0;
        __syncthreads(); sh[t] += u; __syncthreads();
    }
    g_bsumx[t] = sh[t] - v;
}
__global__ void k_scanC() {
    int t = threadIdx.x, i = blockIdx.x * 1024 + t;
    if (i < N_NODES) g_off[i] += g_bsumx[blockIdx.x];
    if (i == 0) g_off[N_NODES] = N_EDGES;
}
__global__ void k_scatter(const void* __restrict__ e) {
    int i = blockIdx.x * blockDim.x + threadIdx.x;
    if (i < N_EDGES) {
        int d = edge_idx(e, 1, i);
        int p = g_off[d] + atomicAdd(&g_cur[d], 1);
        g_srcs[p] = edge_idx(e, 0, i);
    }
}

// ---------------- fp16 shadow of x ----------------
__global__ void k_tohalf(const float* __restrict__ X) {
    int i = blockIdx.x * blockDim.x + threadIdx.x;
    if (i >= N_NODES * 32) return;
    float4 v = ((const float4*)X)[i];
    g_H0[i * 2]     = __floats2half2_rn(v.x, v.y);
    g_H0[i * 2 + 1] = __floats2half2_rn(v.z, v.w);
}

// ---------------- aggregation v2: warp split into 2 halves, uint4 gathers ----------------
__device__ __forceinline__ void add8(float* a, uint4 u) {
    float2 f;
    f = __half22float2(*(__half2*)&u.x); a[0] += f.x; a[1] += f.y;
    f = __half22float2(*(__half2*)&u.y); a[2] += f.x; a[3] += f.y;
    f = __half22float2(*(__half2*)&u.z); a[4] += f.x; a[5] += f.y;
    f = __half22float2(*(__half2*)&u.w); a[6] += f.x; a[7] += f.y;
}

__global__ void k_agg2(int src_sel) {
    int warp = (blockIdx.x * blockDim.x + threadIdx.x) >> 5;
    if (warp >= N_NODES) return;
    int lane = threadIdx.x & 31;
    int half = lane >> 4, li = lane & 15;
    const uint4* H = (const uint4*)(src_sel ? g_H1 : g_H0);
    uint4* T = (uint4*)g_T;

    float a[8];
    #pragma unroll
    for (int i = 0; i < 8; i++) a[i] = 0.f;
    if (half == 0) add8(a, H[(size_t)warp * 16 + li]);   // self term

    int e0 = g_off[warp], e1 = g_off[warp + 1];
    int e = e0;
    for (; e + 4 <= e1; e += 4) {
        int sA = g_srcs[e + half];
        int sB = g_srcs[e + 2 + half];
        uint4 uA = __ldg(&H[(size_t)sA * 16 + li]);
        uint4 uB = __ldg(&H[(size_t)sB * 16 + li]);
        add8(a, uA);
        add8(a, uB);
    }
    for (; e + 2 <= e1; e += 2) {
        int s = g_srcs[e + half];
        uint4 u = __ldg(&H[(size_t)s * 16 + li]);
        add8(a, u);
    }
    if (e < e1 && half == 0) {
        int s = g_srcs[e];
        uint4 u = __ldg(&H[(size_t)s * 16 + li]);
        add8(a, u);
    }
    // combine halves
    #pragma unroll
    for (int i = 0; i < 8; i++) a[i] += __shfl_xor_sync(0xffffffffu, a[i], 16);

    if (half == 0) {
        uint4 o;
        __half2 h;
        h = __floats2half2_rn(a[0], a[1]); o.x = *(uint32_t*)&h;
        h = __floats2half2_rn(a[2], a[3]); o.y = *(uint32_t*)&h;
        h = __floats2half2_rn(a[4], a[5]); o.z = *(uint32_t*)&h;
        h = __floats2half2_rn(a[6], a[7]); o.w = *(uint32_t*)&h;
        T[(size_t)warp * 16 + li] = o;
    }
}

// ---------------- weight image prep (padded fp16 B image, single plane) ----------------
__global__ void k_wimg(const float* __restrict__ W1, const float* __restrict__ W2) {
    int idx = blockIdx.x * blockDim.x + threadIdx.x;  // 6 * 128 * 64
    if (idx >= 6 * 128 * 64) return;
    int mat = idx >> 13;
    int rem = idx & 8191;
    int n = rem >> 6;              // output column = B row
    int kp = rem & 63;             // k pair
    int k = kp * 2;
    int layer = mat >> 1, which = mat & 1;
    const float* Wsrc = (which ? W2 : W1) + (size_t)layer * DIM * DIM;
    __half2 p = __floats2half2_rn(Wsrc[k * DIM + n], Wsrc[(k + 1) * DIM + n]);
    *(uint32_t*)&g_Wimg[mat * WIMG_MAT + n * 272 + kp * 4] = *(uint32_t*)&p;
}

// ---------------- fused 2-GEMM MLP (HMMA fp16, single pass) ----------------
// In: g_T (fp16). Z = relu(BN(T@W1+b1)); Y = relu(Z@W2+b2).
// Out: write_half ? fp16 shadow (H0/H1) : fp32 g_bufF.
#define A_OFF 1536
#define B1_OFF (A_OFF + WIMG_MAT)
#define B2_OFF (B1_OFF + WIMG_MAT)
#define TC_SMEM (B2_OFF + WIMG_MAT)

__device__ __forceinline__ void ldsm4(uint32_t addr, uint32_t* r) {
    asm volatile("ldmatrix.sync.aligned.m8n8.x4.shared.b16 {%0,%1,%2,%3}, [%4];"
                 : "=r"(r[0]), "=r"(r[1]), "=r"(r[2]), "=r"(r[3]) : "r"(addr));
}
__device__ __forceinline__ void mma16816(float* c, const uint32_t* a,
                                         uint32_t b0, uint32_t b1) {
    asm volatile("mma.sync.aligned.m16n8k16.row.col.f32.f16.f16.f32 "
                 "{%0,%1,%2,%3}, {%4,%5,%6,%7}, {%8,%9}, {%0,%1,%2,%3};"
                 : "+f"(c[0]), "+f"(c[1]), "+f"(c[2]), "+f"(c[3])
                 : "r"(a[0]), "r"(a[1]), "r"(a[2]), "r"(a[3]), "r"(b0), "r"(b1));
}

__global__ void __launch_bounds__(512, 2)
k_mlp_fused(int dst_sel, int write_half, int mat1, int mat2,
            const float* __restrict__ b1, const float* __restrict__ gamma,
            const float* __restrict__ beta, const float* __restrict__ mean,
            const float* __restrict__ var, const float* __restrict__ b2) {
    extern __shared__ char smem[];
    uint32_t sbase = smem_u32(smem);
    int tid = threadIdx.x;
    int wid = tid >> 5, lane = tid & 31;
    int row0 = blockIdx.x * 128;
    __half2* Hout = dst_sel ? g_H1 : g_H0;

    // headers
    if (tid < 128) {
        int c = tid;
        float s = gamma[c] * rsqrtf(var[c] + BN_EPS);
        *(float*)(smem + c * 4) = s;
        *(float*)(smem + 512 + c * 4) = (b1[c] - mean[c]) * s + beta[c];
        *(float*)(smem + 1024 + c * 4) = b2[c];
    }
    // stage W1 + W2 images (flat copies)
    {
        const float4* s1 = (const float4*)(g_Wimg + (size_t)mat1 * WIMG_MAT);
        const float4* s2 = (const float4*)(g_Wimg + (size_t)mat2 * WIMG_MAT);
        float4* d1 = (float4*)(smem + B1_OFF);
        float4* d2 = (float4*)(smem + B2_OFF);
        for (int i = tid; i < WIMG_MAT / 16; i += 512) { d1[i] = s1[i]; d2[i] = s2[i]; }
    }
    // stage A: pure fp16 copy from g_T (4 threads per row, 4 x uint4 each)
    {
        int r = tid >> 2, q = tid & 3;
        bool valid = (row0 + r) < N_NODES;
        const uint4* tr = (const uint4*)g_T + (size_t)(row0 + r) * 16 + q * 4;
        char* arow = smem + A_OFF + r * 272 + q * 64;
        #pragma unroll
        for (int j = 0; j < 4; j++) {
            uint4 v = valid ? __ldg(&tr[j]) : make_uint4(0, 0, 0, 0);
            *(uint4*)(arow + j * 16) = v;
        }
    }
    __syncthreads();

    int wm = wid & 3, wn = wid >> 2;
    float acc[2][4][4];
    uint32_t addrA[2], addrBrel[2];
    #pragma unroll
    for (int mt = 0; mt < 2; mt++)
        addrA[mt] = sbase + A_OFF + (wm * 32 + mt * 16 + (lane & 15)) * 272
                    + (lane >> 4) * 16;
    #pragma unroll
    for (int ntp = 0; ntp < 2; ntp++) {
        int quad = lane >> 3;
        int n = wn * 32 + ntp * 16 + (quad >> 1) * 8 + (lane & 7);
        addrBrel[ntp] = n * 272 + (quad & 1) * 16;
    }

    #define GEMM1P(BOFFBASE)                                                       \
    {                                                                              \
        _Pragma("unroll")                                                          \
        for (int mt = 0; mt < 2; mt++)                                             \
            _Pragma("unroll")                                                      \
            for (int nt = 0; nt < 4; nt++)                                         \
                _Pragma("unroll")                                                  \
                for (int j = 0; j < 4; j++) acc[mt][nt][j] = 0.f;                  \
        _Pragma("unroll")                                                          \
        for (int ks = 0; ks < 8; ks++) {                                           \
            uint32_t ko = ks * 32;                                                 \
            uint32_t afr[2][4], bfr[2][4];                                         \
            _Pragma("unroll")                                                      \
            for (int mt = 0; mt < 2; mt++) ldsm4(addrA[mt] + ko, afr[mt]);         \
            _Pragma("unroll")                                                      \
            for (int ntp = 0; ntp < 2; ntp++)                                      \
                ldsm4(sbase + addrBrel[ntp] + (BOFFBASE) + ko, bfr[ntp]);          \
            _Pragma("unroll")                                                      \
            for (int mt = 0; mt < 2; mt++)                                         \
                _Pragma("unroll")                                                  \
                for (int nt = 0; nt < 4; nt++)                                     \
                    mma16816(acc[mt][nt], afr[mt],                                 \
                             bfr[nt >> 1][(nt & 1) * 2],                           \
                             bfr[nt >> 1][(nt & 1) * 2 + 1]);                      \
        }                                                                          \
    }

    // GEMM1
    GEMM1P(B1_OFF);
    __syncthreads();

    // epilogue1: BN+ReLU -> fp16 Z plane (overwrite A region)
    {
        char* base = smem + A_OFF;
        #pragma unroll
        for (int mt = 0; mt < 2; mt++) {
            #pragma unroll
            for (int nt = 0; nt < 4; nt++) {
                int n = wn * 32 + nt * 8 + (lane & 3) * 2;
                float2 sc = *(float2*)(smem + n * 4);
                float2 sh = *(float2*)(smem + 512 + n * 4);
                int lr1 = wm * 32 + mt * 16 + (lane >> 2);
                int lr2 = lr1 + 8;
                float* c = acc[mt][nt];
                __half2 z1 = __floats2half2_rn(fmaxf(fmaf(c[0], sc.x, sh.x), 0.f),
                                               fmaxf(fmaf(c[1], sc.y, sh.y), 0.f));
                __half2 z2 = __floats2half2_rn(fmaxf(fmaf(c[2], sc.x, sh.x), 0.f),
                                               fmaxf(fmaf(c[3], sc.y, sh.y), 0.f));
                *(uint32_t*)(base + lr1 * 272 + n * 2) = *(uint32_t*)&z1;
                *(uint32_t*)(base + lr2 * 272 + n * 2) = *(uint32_t*)&z2;
            }
        }
    }
    __syncthreads();

    // GEMM2
    GEMM1P(B2_OFF);

    // epilogue2: bias+ReLU -> fp16 shadow (mid layers) or fp32 (last layer)
    #pragma unroll
    for (int mt = 0; mt < 2; mt++) {
        #pragma unroll
        for (int nt = 0; nt < 4; nt++) {
            int n = wn * 32 + nt * 8 + (lane & 3) * 2;
            float2 sh = *(float2*)(smem + 1024 + n * 4);
            int r1 = row0 + wm * 32 + mt * 16 + (lane >> 2);
            int r2 = r1 + 8;
            float* c = acc[mt][nt];
            float o0 = fmaxf(c[0] + sh.x, 0.f);
            float o1 = fmaxf(c[1] + sh.y, 0.f);
            float o2 = fmaxf(c[2] + sh.x, 0.f);
            float o3 = fmaxf(c[3] + sh.y, 0.f);
            if (write_half) {
                if (r1 < N_NODES) Hout[(size_t)r1 * 64 + (n >> 1)] = __floats2half2_rn(o0, o1);
                if (r2 < N_NODES) Hout[(size_t)r2 * 64 + (n >> 1)] = __floats2half2_rn(o2, o3);
            } else {
                if (r1 < N_NODES) *(float2*)(g_bufF + (size_t)r1 * DIM + n) = make_float2(o0, o1);
                if (r2 < N_NODES) *(float2*)(g_bufF + (size_t)r2 * DIM + n) = make_float2(o2, o3);
            }
        }
    }
    #undef GEMM1P
}

// ---------------- log-softmax (warp per row) ----------------
__global__ void k_lsm(float* __restrict__ Y) {
    int warp = (blockIdx.x * blockDim.x + threadIdx.x) >> 5;
    if (warp >= N_NODES) return;
    int lane = threadIdx.x & 31;
    float4 v = ((const float4*)g_bufF)[(size_t)warp * 32 + lane];
    float m = fmaxf(fmaxf(v.x, v.y), fmaxf(v.z, v.w));
    #pragma unroll
    for (int o = 16; o; o >>= 1) m = fmaxf(m, __shfl_xor_sync(0xffffffffu, m, o));
    float s = expf(v.x - m) + expf(v.y - m) + expf(v.z - m) + expf(v.w - m);
    #pragma unroll
    for (int o = 16; o; o >>= 1) s += __shfl_xor_sync(0xffffffffu, s, o);
    float ls = m + logf(s);
    ((float4*)Y)[(size_t)warp * 32 + lane] =
        make_float4(v.x - ls, v.y - ls, v.z - ls, v.w - ls);
}

// ---------------- launch ----------------
extern "C" void kernel_launch(void* const* d_in, const int* in_sizes, int n_in,
                              void* d_out, int out_size) {
    const float* x     = (const float*)d_in[0];
    const void* ei     = d_in[1];
    const float* W1    = (const float*)d_in[2];
    const float* b1    = (const float*)d_in[3];
    const float* gamma = (const float*)d_in[4];
    const float* beta  = (const float*)d_in[5];
    const float* rmean = (const float*)d_in[6];
    const float* rvar  = (const float*)d_in[7];
    const float* W2    = (const float*)d_in[8];
    const float* b2    = (const float*)d_in[9];
    float* out = (float*)d_out;

    cudaFuncSetAttribute(k_mlp_fused, cudaFuncAttributeMaxDynamicSharedMemorySize, TC_SMEM);

    k_detect<<<1, 1024>>>((const int*)ei);
    k_zero<<<(N_NODES + 255) / 256, 256>>>();
    k_wimg<<<(6 * 128 * 64 + 255) / 256, 256>>>(W1, W2);
    k_tohalf<<<(N_NODES * 32 + 255) / 256, 256>>>(x);
    k_hist<<<(N_EDGES + 255) / 256, 256>>>(ei);
    k_scanA<<<98, 1024>>>();
    k_scanB<<<1, 128>>>();
    k_scanC<<<98, 1024>>>();
    k_scatter<<<(N_EDGES + 255) / 256, 256>>>(ei);

    const int AGG_BLOCKS = (N_NODES * 32 + 255) / 256;
    const int MLP_BLOCKS = (N_NODES + 127) / 128;

    // layer l: agg reads H(l&1), writes g_T; mlp reads g_T,
    //          writes H((l&1)^1) for l<2, g_bufF for l==2.
    for (int l = 0; l < N_LAYERS; l++) {
        k_agg2<<<AGG_BLOCKS, 256>>>(l & 1);
        k_mlp_fused<<<MLP_BLOCKS, 512, TC_SMEM>>>((l & 1) ^ 1,
                                                  (l < N_LAYERS - 1) ? 1 : 0,
                                                  l * 2, l * 2 + 1,
                                                  b1 + l * DIM, gamma + l * DIM,
                                                  beta + l * DIM, rmean + l * DIM,
                                                  rvar + l * DIM, b2 + l * DIM);
    }
    k_lsm<<<AGG_BLOCKS, 256>>>(out);
}

// round 14
// speedup vs baseline: 2.5392x; 1.1507x over previous
#include <cuda_runtime.h>
#include <cuda_fp16.h>
#include <stdint.h>
#include <math.h>

#define N_NODES 100000
#define N_EDGES 1600000
#define DIM 128
#define N_LAYERS 3
#define BN_EPS 1e-5f

// ---------------- scratch (static device globals; no allocation) ----------------
__device__ __half2 g_H0[N_NODES * DIM / 2];      // fp16 node features (ping)
__device__ __half2 g_H1[N_NODES * DIM / 2];      // fp16 node features (pong)
__device__ __half2 g_T[N_NODES * DIM / 2];       // fp16 agg output
__device__ int g_cnt[N_NODES];
__device__ int g_cur[N_NODES];
__device__ int g_off[N_NODES + 1];
__device__ int g_srcs[N_EDGES];
__device__ int g_is64;
__device__ int g_bsum[128];
__device__ int g_bsumx[128];
// Pre-built padded SMEM image of B = W^T, single fp16 plane:
// per matrix: 128 n-rows x 136 fp16 (272B, k-major).
#define WIMG_MAT 34816   // 128*272
__device__ unsigned char g_Wimg[6 * WIMG_MAT];

__device__ __forceinline__ uint32_t smem_u32(const void* p) {
    uint32_t a;
    asm("{ .reg .u64 t; cvta.to.shared.u64 t, %1; cvt.u32.u64 %0, t; }" : "=r"(a) : "l"(p));
    return a;
}

// ---------------- edge dtype detection ----------------
__global__ void k_detect(const int* __restrict__ e) {
    __shared__ int s;
    if (threadIdx.x == 0) s = 0;
    __syncthreads();
    int v = e[threadIdx.x * 2 + 1];
    if (v != 0) atomicOr(&s, 1);
    __syncthreads();
    if (threadIdx.x == 0) g_is64 = (s == 0) ? 1 : 0;
}
__device__ __forceinline__ int edge_idx(const void* e, int part, int i) {
    if (g_is64) return (int)((const long long*)e)[(size_t)part * N_EDGES + i];
    return ((const int*)e)[(size_t)part * N_EDGES + i];
}

// ---------------- CSR build ----------------
__global__ void k_zero() {
    int i = blockIdx.x * blockDim.x + threadIdx.x;
    if (i < N_NODES) { g_cnt[i] = 0; g_cur[i] = 0; }
}
__global__ void k_hist(const void* __restrict__ e) {
    int i = blockIdx.x * blockDim.x + threadIdx.x;
    if (i < N_EDGES) atomicAdd(&g_cnt[edge_idx(e, 1, i)], 1);
}
__global__ void k_scanA() {
    __shared__ int sh[1024];
    int t = threadIdx.x, i = blockIdx.x * 1024 + t;
    int v = (i < N_NODES) ? g_cnt[i] : 0;
    sh[t] = v; __syncthreads();
    for (int o = 1; o < 1024; o <<= 1) {
        int u = (t >= o) ? sh[t - o] : 0;
        __syncthreads(); sh[t] += u; __syncthreads();
    }
    if (i < N_NODES) g_off[i] = sh[t] - v;
    if (t == 1023) g_bsum[blockIdx.x] = sh[t];
}
__global__ void k_scanB() {
    __shared__ int sh[128];
    int t = threadIdx.x;
    int v = (t < 98) ? g_bsum[t] : 0;
    sh[t] = v; __syncthreads();
    for (int o = 1; o < 128; o <<= 1) {
        int u = (t >= o) ? sh[t - o] : 0;
        __syncthreads(); sh[t] += u; __syncthreads();
    }
    g_bsumx[t] = sh[t] - v;
}
__global__ void k_scanC() {
    int t = threadIdx.x, i = blockIdx.x * 1024 + t;
    if (i < N_NODES) g_off[i] += g_bsumx[blockIdx.x];
    if (i == 0) g_off[N_NODES] = N_EDGES;
}
__global__ void k_scatter(const void* __restrict__ e) {
    int i = blockIdx.x * blockDim.x + threadIdx.x;
    if (i < N_EDGES) {
        int d = edge_idx(e, 1, i);
        int p = g_off[d] + atomicAdd(&g_cur[d], 1);
        g_srcs[p] = edge_idx(e, 0, i);
    }
}

// ---------------- fp16 shadow of x ----------------
__global__ void k_tohalf(const float* __restrict__ X) {
    int i = blockIdx.x * blockDim.x + threadIdx.x;
    if (i >= N_NODES * 32) return;
    float4 v = ((const float4*)X)[i];
    g_H0[i * 2]     = __floats2half2_rn(v.x, v.y);
    g_H0[i * 2 + 1] = __floats2half2_rn(v.z, v.w);
}

// ---------------- aggregation: warp split into 2 halves, 8 edges in flight ----------------
__device__ __forceinline__ void add8(float* a, uint4 u) {
    float2 f;
    f = __half22float2(*(__half2*)&u.x); a[0] += f.x; a[1] += f.y;
    f = __half22float2(*(__half2*)&u.y); a[2] += f.x; a[3] += f.y;
    f = __half22float2(*(__half2*)&u.z); a[4] += f.x; a[5] += f.y;
    f = __half22float2(*(__half2*)&u.w); a[6] += f.x; a[7] += f.y;
}

__global__ void k_agg2(int src_sel) {
    int warp = (blockIdx.x * blockDim.x + threadIdx.x) >> 5;
    if (warp >= N_NODES) return;
    int lane = threadIdx.x & 31;
    int half = lane >> 4, li = lane & 15;
    const uint4* H = (const uint4*)(src_sel ? g_H1 : g_H0);
    uint4* T = (uint4*)g_T;

    float a[8];
    #pragma unroll
    for (int i = 0; i < 8; i++) a[i] = 0.f;
    if (half == 0) add8(a, H[(size_t)warp * 16 + li]);   // self term

    int e = g_off[warp], e1 = g_off[warp + 1];
    for (; e + 8 <= e1; e += 8) {
        int s0 = g_srcs[e + half];
        int s1 = g_srcs[e + 2 + half];
        int s2 = g_srcs[e + 4 + half];
        int s3 = g_srcs[e + 6 + half];
        uint4 u0 = __ldg(&H[(size_t)s0 * 16 + li]);
        uint4 u1 = __ldg(&H[(size_t)s1 * 16 + li]);
        uint4 u2 = __ldg(&H[(size_t)s2 * 16 + li]);
        uint4 u3 = __ldg(&H[(size_t)s3 * 16 + li]);
        add8(a, u0); add8(a, u1); add8(a, u2); add8(a, u3);
    }
    for (; e + 2 <= e1; e += 2) {
        int s = g_srcs[e + half];
        uint4 u = __ldg(&H[(size_t)s * 16 + li]);
        add8(a, u);
    }
    if (e < e1 && half == 0) {
        int s = g_srcs[e];
        uint4 u = __ldg(&H[(size_t)s * 16 + li]);
        add8(a, u);
    }
    // combine halves
    #pragma unroll
    for (int i = 0; i < 8; i++) a[i] += __shfl_xor_sync(0xffffffffu, a[i], 16);

    if (half == 0) {
        uint4 o;
        __half2 h;
        h = __floats2half2_rn(a[0], a[1]); o.x = *(uint32_t*)&h;
        h = __floats2half2_rn(a[2], a[3]); o.y = *(uint32_t*)&h;
        h = __floats2half2_rn(a[4], a[5]); o.z = *(uint32_t*)&h;
        h = __floats2half2_rn(a[6], a[7]); o.w = *(uint32_t*)&h;
        T[(size_t)warp * 16 + li] = o;
    }
}

// ---------------- weight image prep (padded fp16 B image, single plane) ----------------
__global__ void k_wimg(const float* __restrict__ W1, const float* __restrict__ W2) {
    int idx = blockIdx.x * blockDim.x + threadIdx.x;  // 6 * 128 * 64
    if (idx >= 6 * 128 * 64) return;
    int mat = idx >> 13;
    int rem = idx & 8191;
    int n = rem >> 6;              // output column = B row
    int kp = rem & 63;             // k pair
    int k = kp * 2;
    int layer = mat >> 1, which = mat & 1;
    const float* Wsrc = (which ? W2 : W1) + (size_t)layer * DIM * DIM;
    __half2 p = __floats2half2_rn(Wsrc[k * DIM + n], Wsrc[(k + 1) * DIM + n]);
    *(uint32_t*)&g_Wimg[mat * WIMG_MAT + n * 272 + kp * 4] = *(uint32_t*)&p;
}

// ---------------- fused 2-GEMM MLP (HMMA fp16) + optional log-softmax ----------------
// In: g_T (fp16). Z = relu(BN(T@W1+b1)); Y = relu(Z@W2+b2).
// mid layers: write fp16 shadow (H0/H1). last layer: fused log-softmax -> out (fp32).
#define A_OFF 1536
#define B1_OFF (A_OFF + WIMG_MAT)
#define B2_OFF (B1_OFF + WIMG_MAT)
#define TC_SMEM (B2_OFF + WIMG_MAT)
// last-layer fp32 logits buffer: overlays A+B1 regions (69632 B >= 128*132*4)
#define SF_STRIDE 132

__device__ __forceinline__ void ldsm4(uint32_t addr, uint32_t* r) {
    asm volatile("ldmatrix.sync.aligned.m8n8.x4.shared.b16 {%0,%1,%2,%3}, [%4];"
                 : "=r"(r[0]), "=r"(r[1]), "=r"(r[2]), "=r"(r[3]) : "r"(addr));
}
__device__ __forceinline__ void mma16816(float* c, const uint32_t* a,
                                         uint32_t b0, uint32_t b1) {
    asm volatile("mma.sync.aligned.m16n8k16.row.col.f32.f16.f16.f32 "
                 "{%0,%1,%2,%3}, {%4,%5,%6,%7}, {%8,%9}, {%0,%1,%2,%3};"
                 : "+f"(c[0]), "+f"(c[1]), "+f"(c[2]), "+f"(c[3])
                 : "r"(a[0]), "r"(a[1]), "r"(a[2]), "r"(a[3]), "r"(b0), "r"(b1));
}

__global__ void __launch_bounds__(512, 2)
k_mlp_fused(int dst_sel, int last, int mat1, int mat2,
            const float* __restrict__ b1, const float* __restrict__ gamma,
            const float* __restrict__ beta, const float* __restrict__ mean,
            const float* __restrict__ var, const float* __restrict__ b2,
            float* __restrict__ out) {
    extern __shared__ char smem[];
    uint32_t sbase = smem_u32(smem);
    int tid = threadIdx.x;
    int wid = tid >> 5, lane = tid & 31;
    int row0 = blockIdx.x * 128;
    __half2* Hout = dst_sel ? g_H1 : g_H0;

    // headers
    if (tid < 128) {
        int c = tid;
        float s = gamma[c] * rsqrtf(var[c] + BN_EPS);
        *(float*)(smem + c * 4) = s;
        *(float*)(smem + 512 + c * 4) = (b1[c] - mean[c]) * s + beta[c];
        *(float*)(smem + 1024 + c * 4) = b2[c];
    }
    // stage W1 + W2 images (flat copies)
    {
        const float4* s1 = (const float4*)(g_Wimg + (size_t)mat1 * WIMG_MAT);
        const float4* s2 = (const float4*)(g_Wimg + (size_t)mat2 * WIMG_MAT);
        float4* d1 = (float4*)(smem + B1_OFF);
        float4* d2 = (float4*)(smem + B2_OFF);
        for (int i = tid; i < WIMG_MAT / 16; i += 512) { d1[i] = s1[i]; d2[i] = s2[i]; }
    }
    // stage A: pure fp16 copy from g_T (4 threads per row, 4 x uint4 each)
    {
        int r = tid >> 2, q = tid & 3;
        bool valid = (row0 + r) < N_NODES;
        const uint4* tr = (const uint4*)g_T + (size_t)(row0 + r) * 16 + q * 4;
        char* arow = smem + A_OFF + r * 272 + q * 64;
        #pragma unroll
        for (int j = 0; j < 4; j++) {
            uint4 v = valid ? __ldg(&tr[j]) : make_uint4(0, 0, 0, 0);
            *(uint4*)(arow + j * 16) = v;
        }
    }
    __syncthreads();

    int wm = wid & 3, wn = wid >> 2;
    float acc[2][4][4];
    uint32_t addrA[2], addrBrel[2];
    #pragma unroll
    for (int mt = 0; mt < 2; mt++)
        addrA[mt] = sbase + A_OFF + (wm * 32 + mt * 16 + (lane & 15)) * 272
                    + (lane >> 4) * 16;
    #pragma unroll
    for (int ntp = 0; ntp < 2; ntp++) {
        int quad = lane >> 3;
        int n = wn * 32 + ntp * 16 + (quad >> 1) * 8 + (lane & 7);
        addrBrel[ntp] = n * 272 + (quad & 1) * 16;
    }

    #define GEMM1P(BOFFBASE)                                                       \
    {                                                                              \
        _Pragma("unroll")                                                          \
        for (int mt = 0; mt < 2; mt++)                                             \
            _Pragma("unroll")                                                      \
            for (int nt = 0; nt < 4; nt++)                                         \
                _Pragma("unroll")                                                  \
                for (int j = 0; j < 4; j++) acc[mt][nt][j] = 0.f;                  \
        _Pragma("unroll")                                                          \
        for (int ks = 0; ks < 8; ks++) {                                           \
            uint32_t ko = ks * 32;                                                 \
            uint32_t afr[2][4], bfr[2][4];                                         \
            _Pragma("unroll")                                                      \
            for (int mt = 0; mt < 2; mt++) ldsm4(addrA[mt] + ko, afr[mt]);         \
            _Pragma("unroll")                                                      \
            for (int ntp = 0; ntp < 2; ntp++)                                      \
                ldsm4(sbase + addrBrel[ntp] + (BOFFBASE) + ko, bfr[ntp]);          \
            _Pragma("unroll")                                                      \
            for (int mt = 0; mt < 2; mt++)                                         \
                _Pragma("unroll")                                                  \
                for (int nt = 0; nt < 4; nt++)                                     \
                    mma16816(acc[mt][nt], afr[mt],                                 \
                             bfr[nt >> 1][(nt & 1) * 2],                           \
                             bfr[nt >> 1][(nt & 1) * 2 + 1]);                      \
        }                                                                          \
    }

    // GEMM1
    GEMM1P(B1_OFF);
    __syncthreads();

    // epilogue1: BN+ReLU -> fp16 Z plane (overwrite A region)
    {
        char* base = smem + A_OFF;
        #pragma unroll
        for (int mt = 0; mt < 2; mt++) {
            #pragma unroll
            for (int nt = 0; nt < 4; nt++) {
                int n = wn * 32 + nt * 8 + (lane & 3) * 2;
                float2 sc = *(float2*)(smem + n * 4);
                float2 sh = *(float2*)(smem + 512 + n * 4);
                int lr1 = wm * 32 + mt * 16 + (lane >> 2);
                int lr2 = lr1 + 8;
                float* c = acc[mt][nt];
                __half2 z1 = __floats2half2_rn(fmaxf(fmaf(c[0], sc.x, sh.x), 0.f),
                                               fmaxf(fmaf(c[1], sc.y, sh.y), 0.f));
                __half2 z2 = __floats2half2_rn(fmaxf(fmaf(c[2], sc.x, sh.x), 0.f),
                                               fmaxf(fmaf(c[3], sc.y, sh.y), 0.f));
                *(uint32_t*)(base + lr1 * 272 + n * 2) = *(uint32_t*)&z1;
                *(uint32_t*)(base + lr2 * 272 + n * 2) = *(uint32_t*)&z2;
            }
        }
    }
    __syncthreads();

    // GEMM2
    GEMM1P(B2_OFF);

    if (!last) {
        // epilogue2: bias+ReLU -> fp16 shadow
        #pragma unroll
        for (int mt = 0; mt < 2; mt++) {
            #pragma unroll
            for (int nt = 0; nt < 4; nt++) {
                int n = wn * 32 + nt * 8 + (lane & 3) * 2;
                float2 sh = *(float2*)(smem + 1024 + n * 4);
                int r1 = row0 + wm * 32 + mt * 16 + (lane >> 2);
                int r2 = r1 + 8;
                float* c = acc[mt][nt];
                if (r1 < N_NODES)
                    Hout[(size_t)r1 * 64 + (n >> 1)] =
                        __floats2half2_rn(fmaxf(c[0] + sh.x, 0.f), fmaxf(c[1] + sh.y, 0.f));
                if (r2 < N_NODES)
                    Hout[(size_t)r2 * 64 + (n >> 1)] =
                        __floats2half2_rn(fmaxf(c[2] + sh.x, 0.f), fmaxf(c[3] + sh.y, 0.f));
            }
        }
    } else {
        // epilogue2 + fused log-softmax (fp32 logits through SMEM, A+B1 region)
        __syncthreads();   // GEMM2 ldsm reads of A region complete
        float* Sf = (float*)(smem + A_OFF);
        #pragma unroll
        for (int mt = 0; mt < 2; mt++) {
            #pragma unroll
            for (int nt = 0; nt < 4; nt++) {
                int n = wn * 32 + nt * 8 + (lane & 3) * 2;
                float2 sh = *(float2*)(smem + 1024 + n * 4);
                int lr1 = wm * 32 + mt * 16 + (lane >> 2);
                int lr2 = lr1 + 8;
                float* c = acc[mt][nt];
                *(float2*)&Sf[lr1 * SF_STRIDE + n] =
                    make_float2(fmaxf(c[0] + sh.x, 0.f), fmaxf(c[1] + sh.y, 0.f));
                *(float2*)&Sf[lr2 * SF_STRIDE + n] =
                    make_float2(fmaxf(c[2] + sh.x, 0.f), fmaxf(c[3] + sh.y, 0.f));
            }
        }
        __syncthreads();
        #pragma unroll
        for (int j = 0; j < 8; j++) {
            int r = wid * 8 + j;
            int grow = row0 + r;
            float4 v = *(float4*)&Sf[r * SF_STRIDE + lane * 4];
            float m = fmaxf(fmaxf(v.x, v.y), fmaxf(v.z, v.w));
            #pragma unroll
            for (int o = 16; o; o >>= 1) m = fmaxf(m, __shfl_xor_sync(0xffffffffu, m, o));
            float s = expf(v.x - m) + expf(v.y - m) + expf(v.z - m) + expf(v.w - m);
            #pragma unroll
            for (int o = 16; o; o >>= 1) s += __shfl_xor_sync(0xffffffffu, s, o);
            float ls = m + logf(s);
            if (grow < N_NODES)
                ((float4*)out)[(size_t)grow * 32 + lane] =
                    make_float4(v.x - ls, v.y - ls, v.z - ls, v.w - ls);
        }
    }
    #undef GEMM1P
}

// ---------------- launch ----------------
extern "C" void kernel_launch(void* const* d_in, const int* in_sizes, int n_in,
                              void* d_out, int out_size) {
    const float* x     = (const float*)d_in[0];
    const void* ei     = d_in[1];
    const float* W1    = (const float*)d_in[2];
    const float* b1    = (const float*)d_in[3];
    const float* gamma = (const float*)d_in[4];
    const float* beta  = (const float*)d_in[5];
    const float* rmean = (const float*)d_in[6];
    const float* rvar  = (const float*)d_in[7];
    const float* W2    = (const float*)d_in[8];
    const float* b2    = (const float*)d_in[9];
    float* out = (float*)d_out;

    cudaFuncSetAttribute(k_mlp_fused, cudaFuncAttributeMaxDynamicSharedMemorySize, TC_SMEM);

    k_detect<<<1, 1024>>>((const int*)ei);
    k_zero<<<(N_NODES + 255) / 256, 256>>>();
    k_wimg<<<(6 * 128 * 64 + 255) / 256, 256>>>(W1, W2);
    k_tohalf<<<(N_NODES * 32 + 255) / 256, 256>>>(x);
    k_hist<<<(N_EDGES + 255) / 256, 256>>>(ei);
    k_scanA<<<98, 1024>>>();
    k_scanB<<<1, 128>>>();
    k_scanC<<<98, 1024>>>();
    k_scatter<<<(N_EDGES + 255) / 256, 256>>>(ei);

    const int AGG_BLOCKS = (N_NODES * 32 + 255) / 256;
    const int MLP_BLOCKS = (N_NODES + 127) / 128;

    for (int l = 0; l < N_LAYERS; l++) {
        k_agg2<<<AGG_BLOCKS, 256>>>(l & 1);
        k_mlp_fused<<<MLP_BLOCKS, 512, TC_SMEM>>>((l & 1) ^ 1,
                                                  (l == N_LAYERS - 1) ? 1 : 0,
                                                  l * 2, l * 2 + 1,
                                                  b1 + l * DIM, gamma + l * DIM,
                                                  beta + l * DIM, rmean + l * DIM,
                                                  rvar + l * DIM, b2 + l * DIM, out);
    }
}

// round 15
// speedup vs baseline: 2.5397x; 1.0002x over previous
#include <cuda_runtime.h>
#include <cuda_fp16.h>
#include <stdint.h>
#include <math.h>

#define N_NODES 100000
#define N_EDGES 1600000
#define DIM 128
#define N_LAYERS 3
#define BN_EPS 1e-5f
#define N_TILES 782

// ---------------- scratch (static device globals; no allocation) ----------------
__device__ __half2 g_H0[N_NODES * DIM / 2];      // fp16 node features (ping)
__device__ __half2 g_H1[N_NODES * DIM / 2];      // fp16 node features (pong)
__device__ __half2 g_T[N_NODES * DIM / 2];       // fp16 agg output
__device__ int g_cnt[N_NODES];
__device__ int g_cur[N_NODES];
__device__ int g_off[N_NODES + 1];
__device__ int g_srcs[N_EDGES];
__device__ int g_is64;
__device__ int g_bsum[128];
__device__ int g_bsumx[128];
// Pre-built padded SMEM image of B = W^T, single fp16 plane:
// per matrix: 128 n-rows x 136 fp16 (272B, k-major).
#define WIMG_MAT 34816   // 128*272
__device__ unsigned char g_Wimg[6 * WIMG_MAT];

__device__ __forceinline__ uint32_t smem_u32(const void* p) {
    uint32_t a;
    asm("{ .reg .u64 t; cvta.to.shared.u64 t, %1; cvt.u32.u64 %0, t; }" : "=r"(a) : "l"(p));
    return a;
}

// ---------------- edge dtype detection ----------------
__global__ void k_detect(const int* __restrict__ e) {
    __shared__ int s;
    if (threadIdx.x == 0) s = 0;
    __syncthreads();
    int v = e[threadIdx.x * 2 + 1];
    if (v != 0) atomicOr(&s, 1);
    __syncthreads();
    if (threadIdx.x == 0) g_is64 = (s == 0) ? 1 : 0;
}
__device__ __forceinline__ int edge_idx(const void* e, int part, int i) {
    if (g_is64) return (int)((const long long*)e)[(size_t)part * N_EDGES + i];
    return ((const int*)e)[(size_t)part * N_EDGES + i];
}

// ---------------- CSR build ----------------
__global__ void k_zero() {
    int i = blockIdx.x * blockDim.x + threadIdx.x;
    if (i < N_NODES) { g_cnt[i] = 0; g_cur[i] = 0; }
}
__global__ void k_hist(const void* __restrict__ e) {
    int i = blockIdx.x * blockDim.x + threadIdx.x;
    if (i < N_EDGES) atomicAdd(&g_cnt[edge_idx(e, 1, i)], 1);
}
__global__ void k_scanA() {
    __shared__ int sh[1024];
    int t = threadIdx.x, i = blockIdx.x * 1024 + t;
    int v = (i < N_NODES) ? g_cnt[i] : 0;
    sh[t] = v; __syncthreads();
    for (int o = 1; o < 1024; o <<= 1) {
        int u = (t >= o) ? sh[t - o] : 0;
        __syncthreads(); sh[t] += u; __syncthreads();
    }
    if (i < N_NODES) g_off[i] = sh[t] - v;
    if (t == 1023) g_bsum[blockIdx.x] = sh[t];
}
__global__ void k_scanB() {
    __shared__ int sh[128];
    int t = threadIdx.x;
    int v = (t < 98) ? g_bsum[t] : 0;
    sh[t] = v; __syncthreads();
    for (int o = 1; o < 128; o <<= 1) {
        int u = (t >= o) ? sh[t - o] : 0;
        __syncthreads(); sh[t] += u; __syncthreads();
    }
    g_bsumx[t] = sh[t] - v;
}
__global__ void k_scanC() {
    int t = threadIdx.x, i = blockIdx.x * 1024 + t;
    if (i < N_NODES) g_off[i] += g_bsumx[blockIdx.x];
    if (i == 0) g_off[N_NODES] = N_EDGES;
}
__global__ void k_scatter(const void* __restrict__ e) {
    int i = blockIdx.x * blockDim.x + threadIdx.x;
    if (i < N_EDGES) {
        int d = edge_idx(e, 1, i);
        int p = g_off[d] + atomicAdd(&g_cur[d], 1);
        g_srcs[p] = edge_idx(e, 0, i);
    }
}

// ---------------- fp16 shadow of x ----------------
__global__ void k_tohalf(const float* __restrict__ X) {
    int i = blockIdx.x * blockDim.x + threadIdx.x;
    if (i >= N_NODES * 32) return;
    float4 v = ((const float4*)X)[i];
    g_H0[i * 2]     = __floats2half2_rn(v.x, v.y);
    g_H0[i * 2 + 1] = __floats2half2_rn(v.z, v.w);
}

// ---------------- aggregation: warp split into 2 halves, 16 edges in flight ----------------
__device__ __forceinline__ void add8(float* a, uint4 u) {
    float2 f;
    f = __half22float2(*(__half2*)&u.x); a[0] += f.x; a[1] += f.y;
    f = __half22float2(*(__half2*)&u.y); a[2] += f.x; a[3] += f.y;
    f = __half22float2(*(__half2*)&u.z); a[4] += f.x; a[5] += f.y;
    f = __half22float2(*(__half2*)&u.w); a[6] += f.x; a[7] += f.y;
}

__global__ void k_agg2(int src_sel) {
    int warp = (blockIdx.x * blockDim.x + threadIdx.x) >> 5;
    if (warp >= N_NODES) return;
    int lane = threadIdx.x & 31;
    int half = lane >> 4, li = lane & 15;
    const uint4* H = (const uint4*)(src_sel ? g_H1 : g_H0);
    uint4* T = (uint4*)g_T;

    float a[8];
    #pragma unroll
    for (int i = 0; i < 8; i++) a[i] = 0.f;
    if (half == 0) add8(a, H[(size_t)warp * 16 + li]);   // self term

    int e = g_off[warp], e1 = g_off[warp + 1];
    for (; e + 16 <= e1; e += 16) {
        int s0 = g_srcs[e + half];
        int s1 = g_srcs[e + 2 + half];
        int s2 = g_srcs[e + 4 + half];
        int s3 = g_srcs[e + 6 + half];
        int s4 = g_srcs[e + 8 + half];
        int s5 = g_srcs[e + 10 + half];
        int s6 = g_srcs[e + 12 + half];
        int s7 = g_srcs[e + 14 + half];
        uint4 u0 = __ldg(&H[(size_t)s0 * 16 + li]);
        uint4 u1 = __ldg(&H[(size_t)s1 * 16 + li]);
        uint4 u2 = __ldg(&H[(size_t)s2 * 16 + li]);
        uint4 u3 = __ldg(&H[(size_t)s3 * 16 + li]);
        uint4 u4 = __ldg(&H[(size_t)s4 * 16 + li]);
        uint4 u5 = __ldg(&H[(size_t)s5 * 16 + li]);
        uint4 u6 = __ldg(&H[(size_t)s6 * 16 + li]);
        uint4 u7 = __ldg(&H[(size_t)s7 * 16 + li]);
        add8(a, u0); add8(a, u1); add8(a, u2); add8(a, u3);
        add8(a, u4); add8(a, u5); add8(a, u6); add8(a, u7);
    }
    for (; e + 8 <= e1; e += 8) {
        int s0 = g_srcs[e + half];
        int s1 = g_srcs[e + 2 + half];
        int s2 = g_srcs[e + 4 + half];
        int s3 = g_srcs[e + 6 + half];
        uint4 u0 = __ldg(&H[(size_t)s0 * 16 + li]);
        uint4 u1 = __ldg(&H[(size_t)s1 * 16 + li]);
        uint4 u2 = __ldg(&H[(size_t)s2 * 16 + li]);
        uint4 u3 = __ldg(&H[(size_t)s3 * 16 + li]);
        add8(a, u0); add8(a, u1); add8(a, u2); add8(a, u3);
    }
    for (; e + 2 <= e1; e += 2) {
        int s = g_srcs[e + half];
        uint4 u = __ldg(&H[(size_t)s * 16 + li]);
        add8(a, u);
    }
    if (e < e1 && half == 0) {
        int s = g_srcs[e];
        uint4 u = __ldg(&H[(size_t)s * 16 + li]);
        add8(a, u);
    }
    // combine halves
    #pragma unroll
    for (int i = 0; i < 8; i++) a[i] += __shfl_xor_sync(0xffffffffu, a[i], 16);

    if (half == 0) {
        uint4 o;
        __half2 h;
        h = __floats2half2_rn(a[0], a[1]); o.x = *(uint32_t*)&h;
        h = __floats2half2_rn(a[2], a[3]); o.y = *(uint32_t*)&h;
        h = __floats2half2_rn(a[4], a[5]); o.z = *(uint32_t*)&h;
        h = __floats2half2_rn(a[6], a[7]); o.w = *(uint32_t*)&h;
        T[(size_t)warp * 16 + li] = o;
    }
}

// ---------------- weight image prep (padded fp16 B image, single plane) ----------------
__global__ void k_wimg(const float* __restrict__ W1, const float* __restrict__ W2) {
    int idx = blockIdx.x * blockDim.x + threadIdx.x;  // 6 * 128 * 64
    if (idx >= 6 * 128 * 64) return;
    int mat = idx >> 13;
    int rem = idx & 8191;
    int n = rem >> 6;              // output column = B row
    int kp = rem & 63;             // k pair
    int k = kp * 2;
    int layer = mat >> 1, which = mat & 1;
    const float* Wsrc = (which ? W2 : W1) + (size_t)layer * DIM * DIM;
    __half2 p = __floats2half2_rn(Wsrc[k * DIM + n], Wsrc[(k + 1) * DIM + n]);
    *(uint32_t*)&g_Wimg[mat * WIMG_MAT + n * 272 + kp * 4] = *(uint32_t*)&p;
}

// ---------------- fused 2-GEMM MLP (HMMA fp16) + optional log-softmax ----------------
// In: g_T (fp16). Z = relu(BN(T@W1+b1)); Y = relu(Z@W2+b2).
// mid layers: persistent tile loop, write fp16 shadow (H0/H1).
// last layer: 1 tile per CTA, fused log-softmax -> out (fp32).
#define A_OFF 1536
#define B1_OFF (A_OFF + WIMG_MAT)
#define B2_OFF (B1_OFF + WIMG_MAT)
#define TC_SMEM (B2_OFF + WIMG_MAT)
// last-layer fp32 logits buffer: overlays A+B1 regions (69632 B >= 128*132*4)
#define SF_STRIDE 132

__device__ __forceinline__ void ldsm4(uint32_t addr, uint32_t* r) {
    asm volatile("ldmatrix.sync.aligned.m8n8.x4.shared.b16 {%0,%1,%2,%3}, [%4];"
                 : "=r"(r[0]), "=r"(r[1]), "=r"(r[2]), "=r"(r[3]) : "r"(addr));
}
__device__ __forceinline__ void mma16816(float* c, const uint32_t* a,
                                         uint32_t b0, uint32_t b1) {
    asm volatile("mma.sync.aligned.m16n8k16.row.col.f32.f16.f16.f32 "
                 "{%0,%1,%2,%3}, {%4,%5,%6,%7}, {%8,%9}, {%0,%1,%2,%3};"
                 : "+f"(c[0]), "+f"(c[1]), "+f"(c[2]), "+f"(c[3])
                 : "r"(a[0]), "r"(a[1]), "r"(a[2]), "r"(a[3]), "r"(b0), "r"(b1));
}

__global__ void __launch_bounds__(512, 2)
k_mlp_fused(int dst_sel, int last, int mat1, int mat2,
            const float* __restrict__ b1, const float* __restrict__ gamma,
            const float* __restrict__ beta, const float* __restrict__ mean,
            const float* __restrict__ var, const float* __restrict__ b2,
            float* __restrict__ out) {
    extern __shared__ char smem[];
    uint32_t sbase = smem_u32(smem);
    int tid = threadIdx.x;
    int wid = tid >> 5, lane = tid & 31;
    __half2* Hout = dst_sel ? g_H1 : g_H0;

    // headers
    if (tid < 128) {
        int c = tid;
        float s = gamma[c] * rsqrtf(var[c] + BN_EPS);
        *(float*)(smem + c * 4) = s;
        *(float*)(smem + 512 + c * 4) = (b1[c] - mean[c]) * s + beta[c];
        *(float*)(smem + 1024 + c * 4) = b2[c];
    }
    // stage W1 + W2 images once (flat copies)
    {
        const float4* s1 = (const float4*)(g_Wimg + (size_t)mat1 * WIMG_MAT);
        const float4* s2 = (const float4*)(g_Wimg + (size_t)mat2 * WIMG_MAT);
        float4* d1 = (float4*)(smem + B1_OFF);
        float4* d2 = (float4*)(smem + B2_OFF);
        for (int i = tid; i < WIMG_MAT / 16; i += 512) { d1[i] = s1[i]; d2[i] = s2[i]; }
    }

    int wm = wid & 3, wn = wid >> 2;
    float acc[2][4][4];
    uint32_t addrA[2], addrBrel[2];
    #pragma unroll
    for (int mt = 0; mt < 2; mt++)
        addrA[mt] = sbase + A_OFF + (wm * 32 + mt * 16 + (lane & 15)) * 272
                    + (lane >> 4) * 16;
    #pragma unroll
    for (int ntp = 0; ntp < 2; ntp++) {
        int quad = lane >> 3;
        int n = wn * 32 + ntp * 16 + (quad >> 1) * 8 + (lane & 7);
        addrBrel[ntp] = n * 272 + (quad & 1) * 16;
    }

    #define GEMM1P(BOFFBASE)                                                       \
    {                                                                              \
        _Pragma("unroll")                                                          \
        for (int mt = 0; mt < 2; mt++)                                             \
            _Pragma("unroll")                                                      \
            for (int nt = 0; nt < 4; nt++)                                         \
                _Pragma("unroll")                                                  \
                for (int j = 0; j < 4; j++) acc[mt][nt][j] = 0.f;                  \
        _Pragma("unroll")                                                          \
        for (int ks = 0; ks < 8; ks++) {                                           \
            uint32_t ko = ks * 32;                                                 \
            uint32_t afr[2][4], bfr[2][4];                                         \
            _Pragma("unroll")                                                      \
            for (int mt = 0; mt < 2; mt++) ldsm4(addrA[mt] + ko, afr[mt]);         \
            _Pragma("unroll")                                                      \
            for (int ntp = 0; ntp < 2; ntp++)                                      \
                ldsm4(sbase + addrBrel[ntp] + (BOFFBASE) + ko, bfr[ntp]);          \
            _Pragma("unroll")                                                      \
            for (int mt = 0; mt < 2; mt++)                                         \
                _Pragma("unroll")                                                  \
                for (int nt = 0; nt < 4; nt++)                                     \
                    mma16816(acc[mt][nt], afr[mt],                                 \
                             bfr[nt >> 1][(nt & 1) * 2],                           \
                             bfr[nt >> 1][(nt & 1) * 2 + 1]);                      \
        }                                                                          \
    }

    for (int tile = blockIdx.x; tile < N_TILES; tile += gridDim.x) {
        int row0 = tile * 128;
        __syncthreads();   // A region free (prev tile's GEMM2 reads done)

        // stage A: pure fp16 copy from g_T (4 threads per row, 4 x uint4 each)
        {
            int r = tid >> 2, q = tid & 3;
            bool valid = (row0 + r) < N_NODES;
            const uint4* tr = (const uint4*)g_T + (size_t)(row0 + r) * 16 + q * 4;
            char* arow = smem + A_OFF + r * 272 + q * 64;
            #pragma unroll
            for (int j = 0; j < 4; j++) {
                uint4 v = valid ? __ldg(&tr[j]) : make_uint4(0, 0, 0, 0);
                *(uint4*)(arow + j * 16) = v;
            }
        }
        __syncthreads();

        // GEMM1
        GEMM1P(B1_OFF);
        __syncthreads();

        // epilogue1: BN+ReLU -> fp16 Z plane (overwrite A region)
        {
            char* base = smem + A_OFF;
            #pragma unroll
            for (int mt = 0; mt < 2; mt++) {
                #pragma unroll
                for (int nt = 0; nt < 4; nt++) {
                    int n = wn * 32 + nt * 8 + (lane & 3) * 2;
                    float2 sc = *(float2*)(smem + n * 4);
                    float2 sh = *(float2*)(smem + 512 + n * 4);
                    int lr1 = wm * 32 + mt * 16 + (lane >> 2);
                    int lr2 = lr1 + 8;
                    float* c = acc[mt][nt];
                    __half2 z1 = __floats2half2_rn(fmaxf(fmaf(c[0], sc.x, sh.x), 0.f),
                                                   fmaxf(fmaf(c[1], sc.y, sh.y), 0.f));
                    __half2 z2 = __floats2half2_rn(fmaxf(fmaf(c[2], sc.x, sh.x), 0.f),
                                                   fmaxf(fmaf(c[3], sc.y, sh.y), 0.f));
                    *(uint32_t*)(base + lr1 * 272 + n * 2) = *(uint32_t*)&z1;
                    *(uint32_t*)(base + lr2 * 272 + n * 2) = *(uint32_t*)&z2;
                }
            }
        }
        __syncthreads();

        // GEMM2
        GEMM1P(B2_OFF);

        if (!last) {
            // epilogue2: bias+ReLU -> fp16 shadow
            #pragma unroll
            for (int mt = 0; mt < 2; mt++) {
                #pragma unroll
                for (int nt = 0; nt < 4; nt++) {
                    int n = wn * 32 + nt * 8 + (lane & 3) * 2;
                    float2 sh = *(float2*)(smem + 1024 + n * 4);
                    int r1 = row0 + wm * 32 + mt * 16 + (lane >> 2);
                    int r2 = r1 + 8;
                    float* c = acc[mt][nt];
                    if (r1 < N_NODES)
                        Hout[(size_t)r1 * 64 + (n >> 1)] =
                            __floats2half2_rn(fmaxf(c[0] + sh.x, 0.f), fmaxf(c[1] + sh.y, 0.f));
                    if (r2 < N_NODES)
                        Hout[(size_t)r2 * 64 + (n >> 1)] =
                            __floats2half2_rn(fmaxf(c[2] + sh.x, 0.f), fmaxf(c[3] + sh.y, 0.f));
                }
            }
        } else {
            // epilogue2 + fused log-softmax (fp32 logits through SMEM, A+B1 region)
            // NOTE: overlays B1 weights; last layer runs 1 tile per CTA (grid = N_TILES)
            __syncthreads();   // GEMM2 ldsm reads of A region complete
            float* Sf = (float*)(smem + A_OFF);
            #pragma unroll
            for (int mt = 0; mt < 2; mt++) {
                #pragma unroll
                for (int nt = 0; nt < 4; nt++) {
                    int n = wn * 32 + nt * 8 + (lane & 3) * 2;
                    float2 sh = *(float2*)(smem + 1024 + n * 4);
                    int lr1 = wm * 32 + mt * 16 + (lane >> 2);
                    int lr2 = lr1 + 8;
                    float* c = acc[mt][nt];
                    *(float2*)&Sf[lr1 * SF_STRIDE + n] =
                        make_float2(fmaxf(c[0] + sh.x, 0.f), fmaxf(c[1] + sh.y, 0.f));
                    *(float2*)&Sf[lr2 * SF_STRIDE + n] =
                        make_float2(fmaxf(c[2] + sh.x, 0.f), fmaxf(c[3] + sh.y, 0.f));
                }
            }
            __syncthreads();
            #pragma unroll
            for (int j = 0; j < 8; j++) {
                int r = wid * 8 + j;
                int grow = row0 + r;
                float4 v = *(float4*)&Sf[r * SF_STRIDE + lane * 4];
                float m = fmaxf(fmaxf(v.x, v.y), fmaxf(v.z, v.w));
                #pragma unroll
                for (int o = 16; o; o >>= 1) m = fmaxf(m, __shfl_xor_sync(0xffffffffu, m, o));
                float s = expf(v.x - m) + expf(v.y - m) + expf(v.z - m) + expf(v.w - m);
                #pragma unroll
                for (int o = 16; o; o >>= 1) s += __shfl_xor_sync(0xffffffffu, s, o);
                float ls = m + logf(s);
                if (grow < N_NODES)
                    ((float4*)out)[(size_t)grow * 32 + lane] =
                        make_float4(v.x - ls, v.y - ls, v.z - ls, v.w - ls);
            }
        }
    }
    #undef GEMM1P
}

// ---------------- launch ----------------
extern "C" void kernel_launch(void* const* d_in, const int* in_sizes, int n_in,
                              void* d_out, int out_size) {
    const float* x     = (const float*)d_in[0];
    const void* ei     = d_in[1];
    const float* W1    = (const float*)d_in[2];
    const float* b1    = (const float*)d_in[3];
    const float* gamma = (const float*)d_in[4];
    const float* beta  = (const float*)d_in[5];
    const float* rmean = (const float*)d_in[6];
    const float* rvar  = (const float*)d_in[7];
    const float* W2    = (const float*)d_in[8];
    const float* b2    = (const float*)d_in[9];
    float* out = (float*)d_out;

    cudaFuncSetAttribute(k_mlp_fused, cudaFuncAttributeMaxDynamicSharedMemorySize, TC_SMEM);

    k_detect<<<1, 1024>>>((const int*)ei);
    k_zero<<<(N_NODES + 255) / 256, 256>>>();
    k_wimg<<<(6 * 128 * 64 + 255) / 256, 256>>>(W1, W2);
    k_tohalf<<<(N_NODES * 32 + 255) / 256, 256>>>(x);
    k_hist<<<(N_EDGES + 255) / 256, 256>>>(ei);
    k_scanA<<<98, 1024>>>();
    k_scanB<<<1, 128>>>();
    k_scanC<<<98, 1024>>>();
    k_scatter<<<(N_EDGES + 255) / 256, 256>>>(ei);

    const int AGG_BLOCKS = (N_NODES * 32 + 255) / 256;

    for (int l = 0; l < N_LAYERS; l++) {
        int last = (l == N_LAYERS - 1);
        k_agg2<<<AGG_BLOCKS, 256>>>(l & 1);
        k_mlp_fused<<<last ? N_TILES : 296, 512, TC_SMEM>>>(
            (l & 1) ^ 1, last, l * 2, l * 2 + 1,
            b1 + l * DIM, gamma + l * DIM, beta + l * DIM,
            rmean + l * DIM, rvar + l * DIM, b2 + l * DIM, out);
    }
}

// round 17
// speedup vs baseline: 2.5762x; 1.0144x over previous
#include <cuda_runtime.h>
#include <cuda_fp16.h>
#include <stdint.h>
#include <math.h>

#define N_NODES 100000
#define N_EDGES 1600000
#define DIM 128
#define N_LAYERS 3
#define BN_EPS 1e-5f
#define N_TILES 782

// ---------------- scratch (static device globals; no allocation) ----------------
__device__ __half2 g_H0[N_NODES * DIM / 2];      // fp16 node features (ping)
__device__ __half2 g_H1[N_NODES * DIM / 2];      // fp16 node features (pong)
__device__ __half2 g_T[N_NODES * DIM / 2];       // fp16 agg output
__device__ int g_cnt[N_NODES];
__device__ int g_cur[N_NODES];
__device__ int g_off[N_NODES + 1];
__device__ int g_srcs[N_EDGES];
__device__ int g_bsum[128];
__device__ int g_bsumx[128];
// Pre-built padded SMEM image of B = W^T, single fp16 plane:
// per matrix: 128 n-rows x 136 fp16 (272B, k-major).
#define WIMG_MAT 34816   // 128*272
__device__ unsigned char g_Wimg[6 * WIMG_MAT];

__device__ __forceinline__ uint32_t smem_u32(const void* p) {
    uint32_t a;
    asm("{ .reg .u64 t; cvta.to.shared.u64 t, %1; cvt.u32.u64 %0, t; }" : "=r"(a) : "l"(p));
    return a;
}

// ---------------- inline edge dtype detection ----------------
// int64 layout => odd words of the first 4 indices are all 0 (indices < 1e5).
// int32 layout => those words are random node ids; P(all zero) ~ 1e-20.
__device__ __forceinline__ int detect64(const int* __restrict__ e) {
    return ((e[1] | e[3] | e[5] | e[7]) == 0) ? 1 : 0;
}
__device__ __forceinline__ int edge_at(const void* e, int is64, int part, int i) {
    if (is64) return (int)((const long long*)e)[(size_t)part * N_EDGES + i];
    return ((const int*)e)[(size_t)part * N_EDGES + i];
}

// ---------------- merged prep: tohalf | zero | wimg ----------------
__global__ void k_prep0(const float* __restrict__ X,
                        const float* __restrict__ W1, const float* __restrict__ W2) {
    int b = blockIdx.x;
    if (b < 12500) {
        // fp16 shadow of x: 12500 * 256 = 3.2M float4s exactly
        int i = b * 256 + threadIdx.x;
        float4 v = ((const float4*)X)[i];
        g_H0[i * 2]     = __floats2half2_rn(v.x, v.y);
        g_H0[i * 2 + 1] = __floats2half2_rn(v.z, v.w);
    } else if (b < 12500 + 391) {
        int i = (b - 12500) * 256 + threadIdx.x;
        if (i < N_NODES) { g_cnt[i] = 0; g_cur[i] = 0; }
    } else {
        int idx = (b - 12891) * 256 + threadIdx.x;   // 6*128*64 = 49152 = 192 blocks
        if (idx < 6 * 128 * 64) {
            int mat = idx >> 13;
            int rem = idx & 8191;
            int n = rem >> 6;
            int kp = rem & 63;
            int k = kp * 2;
            int layer = mat >> 1, which = mat & 1;
            const float* Wsrc = (which ? W2 : W1) + (size_t)layer * DIM * DIM;
            __half2 p = __floats2half2_rn(Wsrc[k * DIM + n], Wsrc[(k + 1) * DIM + n]);
            *(uint32_t*)&g_Wimg[mat * WIMG_MAT + n * 272 + kp * 4] = *(uint32_t*)&p;
        }
    }
}

// ---------------- CSR build ----------------
__global__ void k_hist(const void* __restrict__ e) {
    int is64 = detect64((const int*)e);
    int i = blockIdx.x * blockDim.x + threadIdx.x;
    if (i < N_EDGES) atomicAdd(&g_cnt[edge_at(e, is64, 1, i)], 1);
}
__global__ void k_scanA() {
    __shared__ int sh[1024];
    int t = threadIdx.x, i = blockIdx.x * 1024 + t;
    int v = (i < N_NODES) ? g_cnt[i] : 0;
    sh[t] = v; __syncthreads();
    for (int o = 1; o < 1024; o <<= 1) {
        int u = (t >= o) ? sh[t - o] : 0;
        __syncthreads(); sh[t] += u; __syncthreads();
    }
    if (i < N_NODES) g_off[i] = sh[t] - v;
    if (t == 1023) g_bsum[blockIdx.x] = sh[t];
}
__global__ void k_scanB() {
    __shared__ int sh[128];
    int t = threadIdx.x;
    int v = (t < 98) ? g_bsum[t] : 0;
    sh[t] = v; __syncthreads();
    for (int o = 1; o < 128; o <<= 1) {
        int u = (t >= o) ? sh[t - o] : 0;
        __syncthreads(); sh[t] += u; __syncthreads();
    }
    g_bsumx[t] = sh[t] - v;
}
__global__ void k_scanC() {
    int t = threadIdx.x, i = blockIdx.x * 1024 + t;
    if (i < N_NODES) g_off[i] += g_bsumx[blockIdx.x];
    if (i == 0) g_off[N_NODES] = N_EDGES;
}
__global__ void k_scatter(const void* __restrict__ e) {
    int is64 = detect64((const int*)e);
    int i = blockIdx.x * blockDim.x + threadIdx.x;
    if (i < N_EDGES) {
        int d = edge_at(e, is64, 1, i);
        int p = g_off[d] + atomicAdd(&g_cur[d], 1);
        g_srcs[p] = edge_at(e, is64, 0, i);
    }
}

// ---------------- aggregation: warp split into 2 halves, 8 gathers in flight ----------------
__device__ __forceinline__ void add8(float* a, uint4 u) {
    float2 f;
    f = __half22float2(*(__half2*)&u.x); a[0] += f.x; a[1] += f.y;
    f = __half22float2(*(__half2*)&u.y); a[2] += f.x; a[3] += f.y;
    f = __half22float2(*(__half2*)&u.z); a[4] += f.x; a[5] += f.y;
    f = __half22float2(*(__half2*)&u.w); a[6] += f.x; a[7] += f.y;
}

__global__ void k_agg2(int src_sel) {
    int warp = (blockIdx.x * blockDim.x + threadIdx.x) >> 5;
    if (warp >= N_NODES) return;
    int lane = threadIdx.x & 31;
    int half = lane >> 4, li = lane & 15;
    const uint4* H = (const uint4*)(src_sel ? g_H1 : g_H0);
    uint4* T = (uint4*)g_T;

    float a[8];
    #pragma unroll
    for (int i = 0; i < 8; i++) a[i] = 0.f;
    if (half == 0) add8(a, H[(size_t)warp * 16 + li]);   // self term

    int e = g_off[warp], e1 = g_off[warp + 1];
    for (; e + 16 <= e1; e += 16) {
        int s0 = g_srcs[e + half];
        int s1 = g_srcs[e + 2 + half];
        int s2 = g_srcs[e + 4 + half];
        int s3 = g_srcs[e + 6 + half];
        int s4 = g_srcs[e + 8 + half];
        int s5 = g_srcs[e + 10 + half];
        int s6 = g_srcs[e + 12 + half];
        int s7 = g_srcs[e + 14 + half];
        uint4 u0 = __ldg(&H[(size_t)s0 * 16 + li]);
        uint4 u1 = __ldg(&H[(size_t)s1 * 16 + li]);
        uint4 u2 = __ldg(&H[(size_t)s2 * 16 + li]);
        uint4 u3 = __ldg(&H[(size_t)s3 * 16 + li]);
        uint4 u4 = __ldg(&H[(size_t)s4 * 16 + li]);
        uint4 u5 = __ldg(&H[(size_t)s5 * 16 + li]);
        uint4 u6 = __ldg(&H[(size_t)s6 * 16 + li]);
        uint4 u7 = __ldg(&H[(size_t)s7 * 16 + li]);
        add8(a, u0); add8(a, u1); add8(a, u2); add8(a, u3);
        add8(a, u4); add8(a, u5); add8(a, u6); add8(a, u7);
    }
    for (; e + 8 <= e1; e += 8) {
        int s0 = g_srcs[e + half];
        int s1 = g_srcs[e + 2 + half];
        int s2 = g_srcs[e + 4 + half];
        int s3 = g_srcs[e + 6 + half];
        uint4 u0 = __ldg(&H[(size_t)s0 * 16 + li]);
        uint4 u1 = __ldg(&H[(size_t)s1 * 16 + li]);
        uint4 u2 = __ldg(&H[(size_t)s2 * 16 + li]);
        uint4 u3 = __ldg(&H[(size_t)s3 * 16 + li]);
        add8(a, u0); add8(a, u1); add8(a, u2); add8(a, u3);
    }
    for (; e + 2 <= e1; e += 2) {
        int s = g_srcs[e + half];
        uint4 u = __ldg(&H[(size_t)s * 16 + li]);
        add8(a, u);
    }
    if (e < e1 && half == 0) {
        int s = g_srcs[e];
        uint4 u = __ldg(&H[(size_t)s * 16 + li]);
        add8(a, u);
    }
    #pragma unroll
    for (int i = 0; i < 8; i++) a[i] += __shfl_xor_sync(0xffffffffu, a[i], 16);

    if (half == 0) {
        uint4 o;
        __half2 h;
        h = __floats2half2_rn(a[0], a[1]); o.x = *(uint32_t*)&h;
        h = __floats2half2_rn(a[2], a[3]); o.y = *(uint32_t*)&h;
        h = __floats2half2_rn(a[4], a[5]); o.z = *(uint32_t*)&h;
        h = __floats2half2_rn(a[6], a[7]); o.w = *(uint32_t*)&h;
        T[(size_t)warp * 16 + li] = o;
    }
}

// ---------------- fused 2-GEMM MLP (HMMA fp16), persistent, optional reg-space lsm ----------------
#define A_OFF 1536
#define B1_OFF (A_OFF + WIMG_MAT)
#define B2_OFF (B1_OFF + WIMG_MAT)
#define TC_SMEM (B2_OFF + WIMG_MAT)

__device__ __forceinline__ void ldsm4(uint32_t addr, uint32_t* r) {
    asm volatile("ldmatrix.sync.aligned.m8n8.x4.shared.b16 {%0,%1,%2,%3}, [%4];"
                 : "=r"(r[0]), "=r"(r[1]), "=r"(r[2]), "=r"(r[3]) : "r"(addr));
}
__device__ __forceinline__ void mma16816(float* c, const uint32_t* a,
                                         uint32_t b0, uint32_t b1) {
    asm volatile("mma.sync.aligned.m16n8k16.row.col.f32.f16.f16.f32 "
                 "{%0,%1,%2,%3}, {%4,%5,%6,%7}, {%8,%9}, {%0,%1,%2,%3};"
                 : "+f"(c[0]), "+f"(c[1]), "+f"(c[2]), "+f"(c[3])
                 : "r"(a[0]), "r"(a[1]), "r"(a[2]), "r"(a[3]), "r"(b0), "r"(b1));
}

__global__ void __launch_bounds__(512, 2)
k_mlp_fused(int dst_sel, int last, int mat1, int mat2,
            const float* __restrict__ b1, const float* __restrict__ gamma,
            const float* __restrict__ beta, const float* __restrict__ mean,
            const float* __restrict__ var, const float* __restrict__ b2,
            float* __restrict__ out) {
    extern __shared__ char smem[];
    uint32_t sbase = smem_u32(smem);
    int tid = threadIdx.x;
    int wid = tid >> 5, lane = tid & 31;
    __half2* Hout = dst_sel ? g_H1 : g_H0;

    // headers
    if (tid < 128) {
        int c = tid;
        float s = gamma[c] * rsqrtf(var[c] + BN_EPS);
        *(float*)(smem + c * 4) = s;
        *(float*)(smem + 512 + c * 4) = (b1[c] - mean[c]) * s + beta[c];
        *(float*)(smem + 1024 + c * 4) = b2[c];
    }
    // stage W1 + W2 images once
    {
        const float4* s1 = (const float4*)(g_Wimg + (size_t)mat1 * WIMG_MAT);
        const float4* s2 = (const float4*)(g_Wimg + (size_t)mat2 * WIMG_MAT);
        float4* d1 = (float4*)(smem + B1_OFF);
        float4* d2 = (float4*)(smem + B2_OFF);
        for (int i = tid; i < WIMG_MAT / 16; i += 512) { d1[i] = s1[i]; d2[i] = s2[i]; }
    }

    int wm = wid & 3, wn = wid >> 2;
    float acc[2][4][4];
    uint32_t addrA[2], addrBrel[2];
    #pragma unroll
    for (int mt = 0; mt < 2; mt++)
        addrA[mt] = sbase + A_OFF + (wm * 32 + mt * 16 + (lane & 15)) * 272
                    + (lane >> 4) * 16;
    #pragma unroll
    for (int ntp = 0; ntp < 2; ntp++) {
        int quad = lane >> 3;
        int n = wn * 32 + ntp * 16 + (quad >> 1) * 8 + (lane & 7);
        addrBrel[ntp] = n * 272 + (quad & 1) * 16;
    }

    // lsm scratch (overlays A region; B1/B2 weights untouched)
    float* scrM = (float*)(smem + A_OFF);          // [128][4]
    float* scrS = (float*)(smem + A_OFF + 2048);   // [128][4]
    float* lsb  = (float*)(smem + A_OFF + 4096);   // [128]

    #define GEMM1P(BOFFBASE)                                                       \
    {                                                                              \
        _Pragma("unroll")                                                          \
        for (int mt = 0; mt < 2; mt++)                                             \
            _Pragma("unroll")                                                      \
            for (int nt = 0; nt < 4; nt++)                                         \
                _Pragma("unroll")                                                  \
                for (int j = 0; j < 4; j++) acc[mt][nt][j] = 0.f;                  \
        _Pragma("unroll")                                                          \
        for (int ks = 0; ks < 8; ks++) {                                           \
            uint32_t ko = ks * 32;                                                 \
            uint32_t afr[2][4], bfr[2][4];                                         \
            _Pragma("unroll")                                                      \
            for (int mt = 0; mt < 2; mt++) ldsm4(addrA[mt] + ko, afr[mt]);         \
            _Pragma("unroll")                                                      \
            for (int ntp = 0; ntp < 2; ntp++)                                      \
                ldsm4(sbase + addrBrel[ntp] + (BOFFBASE) + ko, bfr[ntp]);          \
            _Pragma("unroll")                                                      \
            for (int mt = 0; mt < 2; mt++)                                         \
                _Pragma("unroll")                                                  \
                for (int nt = 0; nt < 4; nt++)                                     \
                    mma16816(acc[mt][nt], afr[mt],                                 \
                             bfr[nt >> 1][(nt & 1) * 2],                           \
                             bfr[nt >> 1][(nt & 1) * 2 + 1]);                      \
        }                                                                          \
    }

    for (int tile = blockIdx.x; tile < N_TILES; tile += gridDim.x) {
        int row0 = tile * 128;
        __syncthreads();   // A region free (prev tile's reads done)

        // stage A: pure fp16 copy from g_T
        {
            int r = tid >> 2, q = tid & 3;
            bool valid = (row0 + r) < N_NODES;
            const uint4* tr = (const uint4*)g_T + (size_t)(row0 + r) * 16 + q * 4;
            char* arow = smem + A_OFF + r * 272 + q * 64;
            #pragma unroll
            for (int j = 0; j < 4; j++) {
                uint4 v = valid ? __ldg(&tr[j]) : make_uint4(0, 0, 0, 0);
                *(uint4*)(arow + j * 16) = v;
            }
        }
        __syncthreads();

        GEMM1P(B1_OFF);
        __syncthreads();

        // epilogue1: BN+ReLU -> fp16 Z plane (overwrite A region)
        {
            char* base = smem + A_OFF;
            #pragma unroll
            for (int mt = 0; mt < 2; mt++) {
                #pragma unroll
                for (int nt = 0; nt < 4; nt++) {
                    int n = wn * 32 + nt * 8 + (lane & 3) * 2;
                    float2 sc = *(float2*)(smem + n * 4);
                    float2 sh = *(float2*)(smem + 512 + n * 4);
                    int lr1 = wm * 32 + mt * 16 + (lane >> 2);
                    int lr2 = lr1 + 8;
                    float* c = acc[mt][nt];
                    __half2 z1 = __floats2half2_rn(fmaxf(fmaf(c[0], sc.x, sh.x), 0.f),
                                                   fmaxf(fmaf(c[1], sc.y, sh.y), 0.f));
                    __half2 z2 = __floats2half2_rn(fmaxf(fmaf(c[2], sc.x, sh.x), 0.f),
                                                   fmaxf(fmaf(c[3], sc.y, sh.y), 0.f));
                    *(uint32_t*)(base + lr1 * 272 + n * 2) = *(uint32_t*)&z1;
                    *(uint32_t*)(base + lr2 * 272 + n * 2) = *(uint32_t*)&z2;
                }
            }
        }
        __syncthreads();

        GEMM1P(B2_OFF);

        // bias + ReLU in registers (both paths)
        #pragma unroll
        for (int mt = 0; mt < 2; mt++) {
            #pragma unroll
            for (int nt = 0; nt < 4; nt++) {
                int n = wn * 32 + nt * 8 + (lane & 3) * 2;
                float2 sh = *(float2*)(smem + 1024 + n * 4);
                float* c = acc[mt][nt];
                c[0] = fmaxf(c[0] + sh.x, 0.f);
                c[1] = fmaxf(c[1] + sh.y, 0.f);
                c[2] = fmaxf(c[2] + sh.x, 0.f);
                c[3] = fmaxf(c[3] + sh.y, 0.f);
            }
        }

        if (!last) {
            #pragma unroll
            for (int mt = 0; mt < 2; mt++) {
                #pragma unroll
                for (int nt = 0; nt < 4; nt++) {
                    int n = wn * 32 + nt * 8 + (lane & 3) * 2;
                    int r1 = row0 + wm * 32 + mt * 16 + (lane >> 2);
                    int r2 = r1 + 8;
                    float* c = acc[mt][nt];
                    if (r1 < N_NODES)
                        Hout[(size_t)r1 * 64 + (n >> 1)] = __floats2half2_rn(c[0], c[1]);
                    if (r2 < N_NODES)
                        Hout[(size_t)r2 * 64 + (n >> 1)] = __floats2half2_rn(c[2], c[3]);
                }
            }
        } else {
            // register-space log-softmax
            __syncthreads();   // GEMM2 ldsm reads of A region complete; overlay scratch
            // 1) per-warp partial max over this warp's 32 cols of each row slot
            #pragma unroll
            for (int mt = 0; mt < 2; mt++) {
                #pragma unroll
                for (int rh = 0; rh < 2; rh++) {
                    float m = -1e30f;
                    #pragma unroll
                    for (int nt = 0; nt < 4; nt++)
                        m = fmaxf(m, fmaxf(acc[mt][nt][rh * 2], acc[mt][nt][rh * 2 + 1]));
                    m = fmaxf(m, __shfl_xor_sync(0xffffffffu, m, 1));
                    m = fmaxf(m, __shfl_xor_sync(0xffffffffu, m, 2));
                    if ((lane & 3) == 0)
                        scrM[(wm * 32 + mt * 16 + rh * 8 + (lane >> 2)) * 4 + wn] = m;
                }
            }
            __syncthreads();
            // 2) global max per row (warp wid handles rows wid*8..+7)
            {
                int r = wid * 8 + (lane >> 2);
                float m = scrM[r * 4 + (lane & 3)];
                m = fmaxf(m, __shfl_xor_sync(0xffffffffu, m, 1));
                m = fmaxf(m, __shfl_xor_sync(0xffffffffu, m, 2));
                if ((lane & 3) == 0) lsb[r] = m;
            }
            __syncthreads();
            // 3) partial sums of exp
            #pragma unroll
            for (int mt = 0; mt < 2; mt++) {
                #pragma unroll
                for (int rh = 0; rh < 2; rh++) {
                    int row = wm * 32 + mt * 16 + rh * 8 + (lane >> 2);
                    float gm = lsb[row];
                    float s = 0.f;
                    #pragma unroll
                    for (int nt = 0; nt < 4; nt++)
                        s += expf(acc[mt][nt][rh * 2] - gm) + expf(acc[mt][nt][rh * 2 + 1] - gm);
                    s += __shfl_xor_sync(0xffffffffu, s, 1);
                    s += __shfl_xor_sync(0xffffffffu, s, 2);
                    if ((lane & 3) == 0) scrS[row * 4 + wn] = s;
                }
            }
            __syncthreads();
            // 4) ls per row
            {
                int r = wid * 8 + (lane >> 2);
                float s = scrS[r * 4 + (lane & 3)];
                s += __shfl_xor_sync(0xffffffffu, s, 1);
                s += __shfl_xor_sync(0xffffffffu, s, 2);
                if ((lane & 3) == 0) lsb[r] = lsb[r] + logf(s);
            }
            __syncthreads();
            // 5) write out
            #pragma unroll
            for (int mt = 0; mt < 2; mt++) {
                #pragma unroll
                for (int nt = 0; nt < 4; nt++) {
                    int n = wn * 32 + nt * 8 + (lane & 3) * 2;
                    int lr1 = wm * 32 + mt * 16 + (lane >> 2);
                    int r1 = row0 + lr1, r2 = r1 + 8;
                    float ls1 = lsb[lr1], ls2 = lsb[lr1 + 8];
                    float* c = acc[mt][nt];
                    if (r1 < N_NODES)
                        *(float2*)(out + (size_t)r1 * DIM + n) =
                            make_float2(c[0] - ls1, c[1] - ls1);
                    if (r2 < N_NODES)
                        *(float2*)(out + (size_t)r2 * DIM + n) =
                            make_float2(c[2] - ls2, c[3] - ls2);
                }
            }
        }
    }
    #undef GEMM1P
}

// ---------------- launch ----------------
extern "C" void kernel_launch(void* const* d_in, const int* in_sizes, int n_in,
                              void* d_out, int out_size) {
    const float* x     = (const float*)d_in[0];
    const void* ei     = d_in[1];
    const float* W1    = (const float*)d_in[2];
    const float* b1    = (const float*)d_in[3];
    const float* gamma = (const float*)d_in[4];
    const float* beta  = (const float*)d_in[5];
    const float* rmean = (const float*)d_in[6];
    const float* rvar  = (const float*)d_in[7];
    const float* W2    = (const float*)d_in[8];
    const float* b2    = (const float*)d_in[9];
    float* out = (float*)d_out;

    cudaFuncSetAttribute(k_mlp_fused, cudaFuncAttributeMaxDynamicSharedMemorySize, TC_SMEM);

    k_prep0<<<12500 + 391 + 192, 256>>>(x, W1, W2);
    k_hist<<<(N_EDGES + 255) / 256, 256>>>(ei);
    k_scanA<<<98, 1024>>>();
    k_scanB<<<1, 128>>>();
    k_scanC<<<98, 1024>>>();
    k_scatter<<<(N_EDGES + 255) / 256, 256>>>(ei);

    const int AGG_BLOCKS = (N_NODES * 32 + 255) / 256;

    for (int l = 0; l < N_LAYERS; l++) {
        int last = (l == N_LAYERS - 1);
        k_agg2<<<AGG_BLOCKS, 256>>>(l & 1);
        k_mlp_fused<<<296, 512, TC_SMEM>>>(
            (l & 1) ^ 1, last, l * 2, l * 2 + 1,
            b1 + l * DIM, gamma + l * DIM, beta + l * DIM,
            rmean + l * DIM, rvar + l * DIM, b2 + l * DIM, out);
    }
}